// round 1
// baseline (speedup 1.0000x reference)
#include <cuda_runtime.h>
#include <cuda_bf16.h>
#include <cstdint>

#define B_   8
#define S_   2048
#define D_   128
#define H_   2
#define ROWS (B_*S_)            // 16384

// ---------------- scratch (static device memory; no allocation) -------------
__device__ float g_qk_in[ROWS*D_];        // LN(x+emb)
__device__ float g_v_in [ROWS*D_];        // LN(x)
__device__ float g_qT[B_*H_*64*S_];       // (b,h,dh,s)
__device__ float g_kT[B_*H_*64*S_];       // (b,h,dh,s)
__device__ float g_v [B_*H_*S_*64];       // (b,h,s,dh)
__device__ float g_ctx[ROWS*D_];          // (b,s,d)
__device__ float g_x2 [ROWS*D_];
__device__ float g_hb [ROWS*2*D_];

// ---------------- fused dual LayerNorm --------------------------------------
// one warp per row (128 elems, 4/thread via float4)
__global__ void __launch_bounds__(256) ln_kernel(
    const float* __restrict__ x, const float* __restrict__ emb,
    const float* __restrict__ g, const float* __restrict__ bta,
    float* __restrict__ qk_in, float* __restrict__ v_in)
{
    int row  = blockIdx.x * 8 + (threadIdx.x >> 5);
    int lane = threadIdx.x & 31;
    size_t base = (size_t)row * 32 + lane;

    float4 xv = ((const float4*)x)[base];
    float4 ev = ((const float4*)emb)[base];
    float4 g4 = ((const float4*)g)[lane];
    float4 b4 = ((const float4*)bta)[lane];

    // ---- LN(x + emb) ----
    float4 t = make_float4(xv.x+ev.x, xv.y+ev.y, xv.z+ev.z, xv.w+ev.w);
    float s = t.x + t.y + t.z + t.w;
    #pragma unroll
    for (int o = 16; o; o >>= 1) s += __shfl_xor_sync(0xffffffffu, s, o);
    float mu = s * (1.0f/128.0f);
    float dx = t.x-mu, dy = t.y-mu, dz = t.z-mu, dw = t.w-mu;
    float v2 = dx*dx + dy*dy + dz*dz + dw*dw;
    #pragma unroll
    for (int o = 16; o; o >>= 1) v2 += __shfl_xor_sync(0xffffffffu, v2, o);
    float r = rsqrtf(v2 * (1.0f/128.0f) + 1e-5f);
    float4 o1 = make_float4(dx*r*g4.x + b4.x, dy*r*g4.y + b4.y,
                            dz*r*g4.z + b4.z, dw*r*g4.w + b4.w);
    ((float4*)qk_in)[base] = o1;

    // ---- LN(x) ----
    s = xv.x + xv.y + xv.z + xv.w;
    #pragma unroll
    for (int o = 16; o; o >>= 1) s += __shfl_xor_sync(0xffffffffu, s, o);
    mu = s * (1.0f/128.0f);
    dx = xv.x-mu; dy = xv.y-mu; dz = xv.z-mu; dw = xv.w-mu;
    v2 = dx*dx + dy*dy + dz*dz + dw*dw;
    #pragma unroll
    for (int o = 16; o; o >>= 1) v2 += __shfl_xor_sync(0xffffffffu, v2, o);
    r = rsqrtf(v2 * (1.0f/128.0f) + 1e-5f);
    float4 o2 = make_float4(dx*r*g4.x + b4.x, dy*r*g4.y + b4.y,
                            dz*r*g4.z + b4.z, dw*r*g4.w + b4.w);
    ((float4*)v_in)[base] = o2;
}

// ---------------- generic 64x64-tile SGEMM, C = A(MxK) * W(NxK)^T + bias ----
// MODE 0: scatter cols 0..255 -> qT/kT (b,h,dh,s) layouts (p0=qT, p1=kT)
// MODE 1: scatter cols 0..127 -> v (b,h,s,dh)           (p0=v)
// MODE 2: out[r,n] = addsrc[r,n] + val
// MODE 3: out[r,n] = 2*relu(val)
template<int MODE>
__global__ void __launch_bounds__(256) gemm_kernel(
    const float* __restrict__ A, const float* __restrict__ W,
    const float* __restrict__ bias, const float* __restrict__ addsrc,
    float* __restrict__ out, int M, int N, int K,
    float* __restrict__ p0, float* __restrict__ p1)
{
    __shared__ float Ast[16*68];
    __shared__ float Wst[16*68];

    int m0 = blockIdx.x * 64, n0 = blockIdx.y * 64;
    int tid = threadIdx.x;
    int ty = tid >> 4, tx = tid & 15;
    int lm = tid >> 2;            // 0..63
    int lk = (tid & 3) * 4;       // 0,4,8,12

    const float* Ald = A + (size_t)(m0 + lm) * K + lk;
    const float* Wld = W + (size_t)(n0 + lm) * K + lk;

    float acc[4][4];
    #pragma unroll
    for (int i = 0; i < 4; i++)
        #pragma unroll
        for (int j = 0; j < 4; j++) acc[i][j] = 0.f;

    for (int kc = 0; kc < K; kc += 16) {
        float4 av = *(const float4*)(Ald + kc);
        float4 wv = *(const float4*)(Wld + kc);
        __syncthreads();
        Ast[(lk+0)*68 + lm] = av.x; Ast[(lk+1)*68 + lm] = av.y;
        Ast[(lk+2)*68 + lm] = av.z; Ast[(lk+3)*68 + lm] = av.w;
        Wst[(lk+0)*68 + lm] = wv.x; Wst[(lk+1)*68 + lm] = wv.y;
        Wst[(lk+2)*68 + lm] = wv.z; Wst[(lk+3)*68 + lm] = wv.w;
        __syncthreads();
        #pragma unroll
        for (int kk = 0; kk < 16; kk++) {
            float4 a4 = *(const float4*)&Ast[kk*68 + 4*ty];
            float4 w4 = *(const float4*)&Wst[kk*68 + 4*tx];
            float a_[4] = {a4.x, a4.y, a4.z, a4.w};
            float w_[4] = {w4.x, w4.y, w4.z, w4.w};
            #pragma unroll
            for (int i = 0; i < 4; i++)
                #pragma unroll
                for (int j = 0; j < 4; j++)
                    acc[i][j] += a_[i] * w_[j];
        }
    }

    #pragma unroll
    for (int i = 0; i < 4; i++) {
        int r = m0 + 4*ty + i;
        #pragma unroll
        for (int j = 0; j < 4; j++) {
            int n = n0 + 4*tx + j;
            float val = acc[i][j] + bias[n];
            if (MODE == 0) {
                int b = r >> 11, sidx = r & 2047;
                int e = n & 127;
                float* base = (n < 128) ? p0 : p1;
                base[((size_t)(b*2 + (e>>6))*64 + (e&63))*2048 + sidx] = val;
            } else if (MODE == 1) {
                int b = r >> 11, sidx = r & 2047;
                p0[((size_t)(b*2 + (n>>6))*2048 + sidx)*64 + (n&63)] = val;
            } else if (MODE == 2) {
                out[(size_t)r*N + n] = addsrc[(size_t)r*N + n] + val;
            } else {
                out[(size_t)r*N + n] = 2.0f * fmaxf(val, 0.f);
            }
        }
    }
}

// ---------------- flash attention (fp32, online softmax) --------------------
// grid: (S/64, B*H), 256 threads; 64x64 Q/K tiles, DH=64
#define SMEM_ATTN ((4096 + 65*64 + 4096)*4 + 320*4)

__global__ void __launch_bounds__(256) flash_attn_kernel(
    const float* __restrict__ qT, const float* __restrict__ kT,
    const float* __restrict__ v,  const int* __restrict__ actions,
    const int* __restrict__ nodeT, float* __restrict__ ctx)
{
    extern __shared__ float sm[];
    float* Qt = sm;               // [dh][qrow] 64x64
    float* KP = Qt + 4096;        // union: Kt[dh*64+kcol] / Ps[kcol*65+qrow]
    float* Vs = KP + 65*64;       // [kcol][dh] 64x64
    int* mac_q = (int*)(Vs + 4096);
    int* job_q = mac_q + 64;
    int* act_q = mac_q + 128;
    int* mac_k = mac_q + 192;
    int* job_k = mac_q + 256;

    int bh = blockIdx.y;
    int b  = bh >> 1;
    int q0 = blockIdx.x * 64;
    int tid = threadIdx.x;
    int ty = tid >> 4, tx = tid & 15;

    const float* qbase = qT + (size_t)bh*64*S_ + q0;
    for (int i = tid; i < 4096; i += 256) {
        int dh = i >> 6, sp = i & 63;
        Qt[dh*64 + sp] = qbase[(size_t)dh*S_ + sp];
    }
    if (tid < 64) {
        mac_q[tid] = nodeT[(q0+tid)*3 + 2];
        job_q[tid] = nodeT[(q0+tid)*3 + 0];
        act_q[tid] = (actions[b*S_ + q0 + tid] == 0);
    }
    __syncthreads();

    int mq[4], jq[4], aq[4];
    #pragma unroll
    for (int i = 0; i < 4; i++) {
        mq[i] = mac_q[4*ty+i]; jq[i] = job_q[4*ty+i]; aq[i] = act_q[4*ty+i];
    }

    float m[4], l[4], O[4][4];
    #pragma unroll
    for (int i = 0; i < 4; i++) {
        m[i] = -1e30f; l[i] = 0.f;
        #pragma unroll
        for (int j = 0; j < 4; j++) O[i][j] = 0.f;
    }

    const float* kbase = kT + (size_t)bh*64*S_;
    const float* vbase = v  + (size_t)bh*S_*64;

    for (int kt = 0; kt < 32; kt++) {
        int k0 = kt * 64;
        __syncthreads();   // previous PV readers done before overwrite
        for (int i = tid; i < 4096; i += 256) {
            int dh = i >> 6, sp = i & 63;
            KP[dh*64 + sp] = kbase[(size_t)dh*S_ + k0 + sp];
            Vs[i] = vbase[(size_t)k0*64 + i];
        }
        if (tid < 64) {
            mac_k[tid] = nodeT[(k0+tid)*3 + 2];
            job_k[tid] = nodeT[(k0+tid)*3 + 0];
        }
        __syncthreads();

        // ---- S = Q K^T ----
        float p[4][4];
        #pragma unroll
        for (int i = 0; i < 4; i++)
            #pragma unroll
            for (int j = 0; j < 4; j++) p[i][j] = 0.f;
        #pragma unroll 8
        for (int dh = 0; dh < 64; dh++) {
            float4 a4 = *(const float4*)&Qt[dh*64 + 4*ty];
            float4 k4 = *(const float4*)&KP[dh*64 + 4*tx];
            float a_[4] = {a4.x, a4.y, a4.z, a4.w};
            float k_[4] = {k4.x, k4.y, k4.z, k4.w};
            #pragma unroll
            for (int i = 0; i < 4; i++)
                #pragma unroll
                for (int j = 0; j < 4; j++)
                    p[i][j] += a_[i] * k_[j];
        }

        int mk[4], jk[4];
        #pragma unroll
        for (int j = 0; j < 4; j++) { mk[j] = mac_k[4*tx+j]; jk[j] = job_k[4*tx+j]; }

        // ---- masked online softmax ----
        #pragma unroll
        for (int i = 0; i < 4; i++) {
            float rmax = -1e30f;
            #pragma unroll
            for (int j = 0; j < 4; j++) {
                float val = p[i][j] * 0.125f;
                if (aq[i] && (mq[i] != mk[j]) && (jq[i] != jk[j])) val = -1e30f;
                p[i][j] = val;
                rmax = fmaxf(rmax, val);
            }
            #pragma unroll
            for (int o = 1; o < 16; o <<= 1)
                rmax = fmaxf(rmax, __shfl_xor_sync(0xffffffffu, rmax, o));
            float mnew = fmaxf(m[i], rmax);
            float corr = __expf(m[i] - mnew);
            m[i] = mnew;
            float rsum = 0.f;
            #pragma unroll
            for (int j = 0; j < 4; j++) {
                float e = __expf(p[i][j] - mnew);
                p[i][j] = e;
                rsum += e;
            }
            #pragma unroll
            for (int o = 1; o < 16; o <<= 1)
                rsum += __shfl_xor_sync(0xffffffffu, rsum, o);
            l[i] = l[i]*corr + rsum;
            #pragma unroll
            for (int j = 0; j < 4; j++) O[i][j] *= corr;
        }

        __syncthreads();   // done reading KP as K-tile
        #pragma unroll
        for (int j = 0; j < 4; j++)
            #pragma unroll
            for (int i = 0; i < 4; i++)
                KP[(4*tx+j)*65 + 4*ty + i] = p[i][j];
        __syncthreads();

        // ---- O += P V ----
        #pragma unroll 8
        for (int kc = 0; kc < 64; kc++) {
            float pr0 = KP[kc*65 + 4*ty + 0];
            float pr1 = KP[kc*65 + 4*ty + 1];
            float pr2 = KP[kc*65 + 4*ty + 2];
            float pr3 = KP[kc*65 + 4*ty + 3];
            float4 v4 = *(const float4*)&Vs[kc*64 + 4*tx];
            O[0][0] += pr0*v4.x; O[0][1] += pr0*v4.y; O[0][2] += pr0*v4.z; O[0][3] += pr0*v4.w;
            O[1][0] += pr1*v4.x; O[1][1] += pr1*v4.y; O[1][2] += pr1*v4.z; O[1][3] += pr1*v4.w;
            O[2][0] += pr2*v4.x; O[2][1] += pr2*v4.y; O[2][2] += pr2*v4.z; O[2][3] += pr2*v4.w;
            O[3][0] += pr3*v4.x; O[3][1] += pr3*v4.y; O[3][2] += pr3*v4.z; O[3][3] += pr3*v4.w;
        }
    }

    int h = bh & 1;
    #pragma unroll
    for (int i = 0; i < 4; i++) {
        float inv = 1.0f / l[i];
        int q = q0 + 4*ty + i;
        float4 o4 = make_float4(O[i][0]*inv, O[i][1]*inv, O[i][2]*inv, O[i][3]*inv);
        *(float4*)&ctx[((size_t)b*S_ + q)*128 + h*64 + 4*tx] = o4;
    }
}

// ---------------- launcher ---------------------------------------------------
extern "C" void kernel_launch(void* const* d_in, const int* in_sizes, int n_in,
                              void* d_out, int out_size)
{
    const float* x    = (const float*)d_in[0];
    const float* emb  = (const float*)d_in[1];
    const int*   act  = (const int*)  d_in[2];
    const int*   node = (const int*)  d_in[3];
    const float* Wqkv = (const float*)d_in[4];
    const float* bqkv = (const float*)d_in[5];
    const float* Wo   = (const float*)d_in[6];
    const float* bo   = (const float*)d_in[7];
    const float* lng  = (const float*)d_in[8];
    const float* lnb  = (const float*)d_in[9];
    const float* W1   = (const float*)d_in[10];
    const float* b1   = (const float*)d_in[11];
    const float* W2   = (const float*)d_in[12];
    const float* b2   = (const float*)d_in[13];
    float* out = (float*)d_out;

    float *qk_in, *v_in, *qT, *kTp, *vv, *ctx, *x2, *hb;
    cudaGetSymbolAddress((void**)&qk_in, g_qk_in);
    cudaGetSymbolAddress((void**)&v_in,  g_v_in);
    cudaGetSymbolAddress((void**)&qT,    g_qT);
    cudaGetSymbolAddress((void**)&kTp,   g_kT);
    cudaGetSymbolAddress((void**)&vv,    g_v);
    cudaGetSymbolAddress((void**)&ctx,   g_ctx);
    cudaGetSymbolAddress((void**)&x2,    g_x2);
    cudaGetSymbolAddress((void**)&hb,    g_hb);

    cudaFuncSetAttribute(flash_attn_kernel,
                         cudaFuncAttributeMaxDynamicSharedMemorySize, SMEM_ATTN);

    // 1) dual LayerNorm
    ln_kernel<<<ROWS/8, 256>>>(x, emb, lng, lnb, qk_in, v_in);

    // 2) Q,K projection (cols 0..255 of in_proj), scattered transposed
    gemm_kernel<0><<<dim3(ROWS/64, 4), 256>>>(qk_in, Wqkv, bqkv, nullptr, nullptr,
                                              ROWS, 256, 128, qT, kTp);
    // 3) V projection (rows 256..383 of in_proj)
    gemm_kernel<1><<<dim3(ROWS/64, 2), 256>>>(v_in, Wqkv + 256*128, bqkv + 256,
                                              nullptr, nullptr, ROWS, 128, 128, vv, nullptr);
    // 4) attention
    flash_attn_kernel<<<dim3(S_/64, B_*H_), 256, SMEM_ATTN>>>(qT, kTp, vv, act, node, ctx);

    // 5) out projection + residual: x2 = x + ctx @ Wo^T + bo
    gemm_kernel<2><<<dim3(ROWS/64, 2), 256>>>(ctx, Wo, bo, x, x2,
                                              ROWS, 128, 128, nullptr, nullptr);
    // 6) FFN1: hb = 2*relu(x2 @ W1^T + b1)
    gemm_kernel<3><<<dim3(ROWS/64, 4), 256>>>(x2, W1, b1, nullptr, hb,
                                              ROWS, 256, 128, nullptr, nullptr);
    // 7) FFN2 + residual: out = x2 + hb @ W2^T + b2
    gemm_kernel<2><<<dim3(ROWS/64, 2), 256>>>(hb, W2, b2, x2, out,
                                              ROWS, 128, 256, nullptr, nullptr);
}

// round 3
// speedup vs baseline: 2.3462x; 2.3462x over previous
#include <cuda_runtime.h>
#include <cuda_bf16.h>
#include <cstdint>

#define B_   8
#define S_   2048
#define D_   128
#define ROWS (B_*S_)            // 16384

// ---------------- scratch (static device memory; no allocation) -------------
__device__ float g_qk_in[ROWS*D_];        // LN(x+emb)
__device__ float g_v_in [ROWS*D_];        // LN(x)
__device__ float g_q [16*S_*64];          // (b,h,s,dh)
__device__ float g_k [16*S_*64];          // (b,h,s,dh)
__device__ float g_v [16*S_*64];          // (b,h,s,dh)
__device__ float g_ctx[ROWS*D_];          // (b,s,d)
__device__ float g_x2 [ROWS*D_];
__device__ float g_hb [ROWS*2*D_];

// ---------------- fused dual LayerNorm --------------------------------------
__global__ void __launch_bounds__(256) ln_kernel(
    const float* __restrict__ x, const float* __restrict__ emb,
    const float* __restrict__ g, const float* __restrict__ bta,
    float* __restrict__ qk_in, float* __restrict__ v_in)
{
    int row  = blockIdx.x * 8 + (threadIdx.x >> 5);
    int lane = threadIdx.x & 31;
    size_t base = (size_t)row * 32 + lane;

    float4 xv = ((const float4*)x)[base];
    float4 ev = ((const float4*)emb)[base];
    float4 g4 = ((const float4*)g)[lane];
    float4 b4 = ((const float4*)bta)[lane];

    float4 t = make_float4(xv.x+ev.x, xv.y+ev.y, xv.z+ev.z, xv.w+ev.w);
    float s = t.x + t.y + t.z + t.w;
    #pragma unroll
    for (int o = 16; o; o >>= 1) s += __shfl_xor_sync(0xffffffffu, s, o);
    float mu = s * (1.0f/128.0f);
    float dx = t.x-mu, dy = t.y-mu, dz = t.z-mu, dw = t.w-mu;
    float v2 = dx*dx + dy*dy + dz*dz + dw*dw;
    #pragma unroll
    for (int o = 16; o; o >>= 1) v2 += __shfl_xor_sync(0xffffffffu, v2, o);
    float r = rsqrtf(v2 * (1.0f/128.0f) + 1e-5f);
    ((float4*)qk_in)[base] = make_float4(dx*r*g4.x + b4.x, dy*r*g4.y + b4.y,
                                         dz*r*g4.z + b4.z, dw*r*g4.w + b4.w);

    s = xv.x + xv.y + xv.z + xv.w;
    #pragma unroll
    for (int o = 16; o; o >>= 1) s += __shfl_xor_sync(0xffffffffu, s, o);
    mu = s * (1.0f/128.0f);
    dx = xv.x-mu; dy = xv.y-mu; dz = xv.z-mu; dw = xv.w-mu;
    v2 = dx*dx + dy*dy + dz*dz + dw*dw;
    #pragma unroll
    for (int o = 16; o; o >>= 1) v2 += __shfl_xor_sync(0xffffffffu, v2, o);
    r = rsqrtf(v2 * (1.0f/128.0f) + 1e-5f);
    ((float4*)v_in)[base] = make_float4(dx*r*g4.x + b4.x, dy*r*g4.y + b4.y,
                                        dz*r*g4.z + b4.z, dw*r*g4.w + b4.w);
}

// ---------------- generic 64x64-tile SGEMM, C = A(MxK) * W(NxK)^T + bias ----
// MODE 0: scatter cols 0..255 -> q,k (b,h,s,dh)  (p0=q, p1=k)
// MODE 1: scatter cols 0..127 -> v (b,h,s,dh)    (p0=v)
// MODE 2: out[r,n] = addsrc[r,n] + val
// MODE 3: out[r,n] = 2*relu(val)
template<int MODE>
__global__ void __launch_bounds__(256) gemm_kernel(
    const float* __restrict__ A, const float* __restrict__ W,
    const float* __restrict__ bias, const float* __restrict__ addsrc,
    float* __restrict__ out, int M, int N, int K,
    float* __restrict__ p0, float* __restrict__ p1)
{
    __shared__ float Ast[16*68];
    __shared__ float Wst[16*68];

    int m0 = blockIdx.x * 64, n0 = blockIdx.y * 64;
    int tid = threadIdx.x;
    int ty = tid >> 4, tx = tid & 15;
    int lm = tid >> 2;
    int lk = (tid & 3) * 4;

    const float* Ald = A + (size_t)(m0 + lm) * K + lk;
    const float* Wld = W + (size_t)(n0 + lm) * K + lk;

    float acc[4][4];
    #pragma unroll
    for (int i = 0; i < 4; i++)
        #pragma unroll
        for (int j = 0; j < 4; j++) acc[i][j] = 0.f;

    for (int kc = 0; kc < K; kc += 16) {
        float4 av = *(const float4*)(Ald + kc);
        float4 wv = *(const float4*)(Wld + kc);
        __syncthreads();
        Ast[(lk+0)*68 + lm] = av.x; Ast[(lk+1)*68 + lm] = av.y;
        Ast[(lk+2)*68 + lm] = av.z; Ast[(lk+3)*68 + lm] = av.w;
        Wst[(lk+0)*68 + lm] = wv.x; Wst[(lk+1)*68 + lm] = wv.y;
        Wst[(lk+2)*68 + lm] = wv.z; Wst[(lk+3)*68 + lm] = wv.w;
        __syncthreads();
        #pragma unroll
        for (int kk = 0; kk < 16; kk++) {
            float4 a4 = *(const float4*)&Ast[kk*68 + 4*ty];
            float4 w4 = *(const float4*)&Wst[kk*68 + 4*tx];
            float a_[4] = {a4.x, a4.y, a4.z, a4.w};
            float w_[4] = {w4.x, w4.y, w4.z, w4.w};
            #pragma unroll
            for (int i = 0; i < 4; i++)
                #pragma unroll
                for (int j = 0; j < 4; j++)
                    acc[i][j] += a_[i] * w_[j];
        }
    }

    #pragma unroll
    for (int i = 0; i < 4; i++) {
        int r = m0 + 4*ty + i;
        #pragma unroll
        for (int j = 0; j < 4; j++) {
            int n = n0 + 4*tx + j;
            float val = acc[i][j] + bias[n];
            if (MODE == 0) {
                int b = r >> 11, sidx = r & 2047;
                int e = n & 127;
                float* base = (n < 128) ? p0 : p1;
                base[((size_t)(b*2 + (e>>6))*2048 + sidx)*64 + (e&63)] = val;
            } else if (MODE == 1) {
                int b = r >> 11, sidx = r & 2047;
                p0[((size_t)(b*2 + (n>>6))*2048 + sidx)*64 + (n&63)] = val;
            } else if (MODE == 2) {
                out[(size_t)r*N + n] = addsrc[(size_t)r*N + n] + val;
            } else {
                out[(size_t)r*N + n] = 2.0f * fmaxf(val, 0.f);
            }
        }
    }
}

// ================= warp-mma tf32 flash attention ============================
// grid (S/128, B*H), 256 threads (8 warps). Q tile 128, K tile 64, DH=64.
// Unnormalized softmax: p = exp2(score*log2e/8) (|score/8| <~ 2), masked -> 0.
#define QSCALE 0.18033688011112042f   // log2(e)/8

__device__ __forceinline__ uint32_t cvt_tf32(float f) {
    uint32_t u;
    asm("cvt.rna.tf32.f32 %0, %1;" : "=r"(u) : "f"(f));
    return u;
}
__device__ __forceinline__ void mma_tf32(float* d, const uint32_t* a, const uint32_t* b) {
    asm volatile("mma.sync.aligned.m16n8k8.row.col.f32.tf32.tf32.f32 "
        "{%0,%1,%2,%3}, {%4,%5,%6,%7}, {%8,%9}, {%0,%1,%2,%3};"
        : "+f"(d[0]), "+f"(d[1]), "+f"(d[2]), "+f"(d[3])
        : "r"(a[0]), "r"(a[1]), "r"(a[2]), "r"(a[3]), "r"(b[0]), "r"(b[1]));
}

// smem (uint32 units): Qs [128][68] @0 ; K [64][68] / P [128][68] union @8704 ;
// Vs [64][72] @17408 ; mj int2[64] @22016. Total 22144 u32 = 88576 B.
#define ATT_SMEM_BYTES 88576

__global__ void __launch_bounds__(256, 2) attn_mma_kernel(
    const float* __restrict__ q, const float* __restrict__ k,
    const float* __restrict__ v, const int* __restrict__ actions,
    const int* __restrict__ nodeT, float* __restrict__ ctx)
{
    extern __shared__ uint32_t sm[];
    uint32_t* Qs = sm;            // [128][68]
    uint32_t* KP = sm + 8704;     // K [64][68] / P [128][68]
    uint32_t* Vs = sm + 17408;    // [64][72]
    int2* mj = (int2*)(sm + 22016);

    int tid = threadIdx.x;
    int w = tid >> 5, lane = tid & 31;
    int g = lane >> 2, tg = lane & 3;
    int bh = blockIdx.y, b = bh >> 1, h = bh & 1;
    int q0 = blockIdx.x * 128;

    // ---- Q tile: scale + cvt to tf32 ----
    const float4* qg = (const float4*)(q + ((size_t)bh * S_ + q0) * 64);
    #pragma unroll
    for (int i = tid; i < 2048; i += 256) {
        int r = i >> 4, c4 = i & 15;
        float4 t = qg[i];
        uint4 u = make_uint4(cvt_tf32(t.x*QSCALE), cvt_tf32(t.y*QSCALE),
                             cvt_tf32(t.z*QSCALE), cvt_tf32(t.w*QSCALE));
        *(uint4*)&Qs[r*68 + c4*4] = u;
    }

    // ---- per-row mask data (rows owned by this thread's fragments) ----
    int rq0 = q0 + 16*w + g, rq1 = rq0 + 8;
    int mq0 = nodeT[rq0*3 + 2], jq0 = nodeT[rq0*3 + 0];
    int mq1 = nodeT[rq1*3 + 2], jq1 = nodeT[rq1*3 + 0];
    int aq0 = (actions[b*S_ + rq0] == 0);
    int aq1 = (actions[b*S_ + rq1] == 0);

    const float4* kg = (const float4*)(k + (size_t)bh * S_ * 64);
    const float4* vg = (const float4*)(v + (size_t)bh * S_ * 64);

    float o[8][4];
    #pragma unroll
    for (int j = 0; j < 8; j++)
        #pragma unroll
        for (int i = 0; i < 4; i++) o[j][i] = 0.f;
    float l0 = 0.f, l1 = 0.f;

    int ar0 = (16*w + g) * 68;       // P/Q row offsets
    int ar1 = ar0 + 8*68;

    for (int kt = 0; kt < 32; kt++) {
        int k0 = kt * 64;
        __syncthreads();   // prev PV done (P union region) / V readable

        // ---- load K,V tiles (cvt tf32) + mask ids ----
        #pragma unroll
        for (int i = tid; i < 1024; i += 256) {
            int r = i >> 4, c4 = i & 15;
            float4 t = kg[k0*16 + i];
            *(uint4*)&KP[r*68 + c4*4] = make_uint4(cvt_tf32(t.x), cvt_tf32(t.y),
                                                   cvt_tf32(t.z), cvt_tf32(t.w));
            float4 tv = vg[k0*16 + i];
            *(uint4*)&Vs[r*72 + c4*4] = make_uint4(cvt_tf32(tv.x), cvt_tf32(tv.y),
                                                   cvt_tf32(tv.z), cvt_tf32(tv.w));
        }
        if (tid < 64)
            mj[tid] = make_int2(nodeT[(k0+tid)*3 + 2], nodeT[(k0+tid)*3 + 0]);
        __syncthreads();

        // ---- S = Q K^T (128x64, k=64) ----
        float c[8][4];
        #pragma unroll
        for (int j = 0; j < 8; j++)
            #pragma unroll
            for (int i = 0; i < 4; i++) c[j][i] = 0.f;
        #pragma unroll
        for (int ks = 0; ks < 8; ks++) {
            int kc = ks*8 + tg;
            uint32_t a[4] = { Qs[ar0 + kc], Qs[ar1 + kc],
                              Qs[ar0 + kc + 4], Qs[ar1 + kc + 4] };
            #pragma unroll
            for (int j = 0; j < 8; j++) {
                uint32_t bf[2] = { KP[(8*j+g)*68 + kc], KP[(8*j+g)*68 + kc + 4] };
                mma_tf32(c[j], a, bf);
            }
        }

        // ---- masked exp (unnormalized) ----
        #pragma unroll
        for (int j = 0; j < 8; j++) {
            int c0 = 8*j + 2*tg, c1 = c0 + 1;
            int2 m0 = mj[c0], m1 = mj[c1];
            float e00, e01, e10, e11;
            asm("ex2.approx.f32 %0, %1;" : "=f"(e00) : "f"(c[j][0]));
            asm("ex2.approx.f32 %0, %1;" : "=f"(e01) : "f"(c[j][1]));
            asm("ex2.approx.f32 %0, %1;" : "=f"(e10) : "f"(c[j][2]));
            asm("ex2.approx.f32 %0, %1;" : "=f"(e11) : "f"(c[j][3]));
            if (aq0 & (mq0 != m0.x) & (jq0 != m0.y)) e00 = 0.f;
            if (aq0 & (mq0 != m1.x) & (jq0 != m1.y)) e01 = 0.f;
            if (aq1 & (mq1 != m0.x) & (jq1 != m0.y)) e10 = 0.f;
            if (aq1 & (mq1 != m1.x) & (jq1 != m1.y)) e11 = 0.f;
            c[j][0] = e00; c[j][1] = e01; c[j][2] = e10; c[j][3] = e11;
            l0 += e00 + e01;
            l1 += e10 + e11;
        }

        __syncthreads();   // all warps done reading K before P overwrites union

        // ---- store P (tf32) ----
        #pragma unroll
        for (int j = 0; j < 8; j++) {
            int c0 = 8*j + 2*tg;
            *(uint2*)&KP[ar0 + c0] = make_uint2(cvt_tf32(c[j][0]), cvt_tf32(c[j][1]));
            *(uint2*)&KP[ar1 + c0] = make_uint2(cvt_tf32(c[j][2]), cvt_tf32(c[j][3]));
        }
        __syncthreads();

        // ---- O += P V (128x64, k=64) ----
        #pragma unroll
        for (int ks = 0; ks < 8; ks++) {
            int sc = ks*8 + tg;
            uint32_t a[4] = { KP[ar0 + sc], KP[ar1 + sc],
                              KP[ar0 + sc + 4], KP[ar1 + sc + 4] };
            #pragma unroll
            for (int j = 0; j < 8; j++) {
                uint32_t bf[2] = { Vs[sc*72 + 8*j + g], Vs[(sc+4)*72 + 8*j + g] };
                mma_tf32(o[j], a, bf);
            }
        }
    }

    // ---- row-sum reduce across quad, normalize, write ----
    #pragma unroll
    for (int off = 1; off < 4; off <<= 1) {
        l0 += __shfl_xor_sync(0xffffffffu, l0, off);
        l1 += __shfl_xor_sync(0xffffffffu, l1, off);
    }
    float inv0 = 1.0f / l0, inv1 = 1.0f / l1;

    float* og0 = ctx + ((size_t)b*S_ + rq0)*128 + h*64;
    float* og1 = ctx + ((size_t)b*S_ + rq1)*128 + h*64;
    #pragma unroll
    for (int j = 0; j < 8; j++) {
        int c0 = 8*j + 2*tg;
        *(float2*)(og0 + c0) = make_float2(o[j][0]*inv0, o[j][1]*inv0);
        *(float2*)(og1 + c0) = make_float2(o[j][2]*inv1, o[j][3]*inv1);
    }
}

// ---------------- launcher ---------------------------------------------------
extern "C" void kernel_launch(void* const* d_in, const int* in_sizes, int n_in,
                              void* d_out, int out_size)
{
    const float* x    = (const float*)d_in[0];
    const float* emb  = (const float*)d_in[1];
    const int*   act  = (const int*)  d_in[2];
    const int*   node = (const int*)  d_in[3];
    const float* Wqkv = (const float*)d_in[4];
    const float* bqkv = (const float*)d_in[5];
    const float* Wo   = (const float*)d_in[6];
    const float* bo   = (const float*)d_in[7];
    const float* lng  = (const float*)d_in[8];
    const float* lnb  = (const float*)d_in[9];
    const float* W1   = (const float*)d_in[10];
    const float* b1   = (const float*)d_in[11];
    const float* W2   = (const float*)d_in[12];
    const float* b2   = (const float*)d_in[13];
    float* out = (float*)d_out;

    float *qk_in, *v_in, *qp, *kp, *vp, *ctx, *x2, *hb;
    cudaGetSymbolAddress((void**)&qk_in, g_qk_in);
    cudaGetSymbolAddress((void**)&v_in,  g_v_in);
    cudaGetSymbolAddress((void**)&qp,    g_q);
    cudaGetSymbolAddress((void**)&kp,    g_k);
    cudaGetSymbolAddress((void**)&vp,    g_v);
    cudaGetSymbolAddress((void**)&ctx,   g_ctx);
    cudaGetSymbolAddress((void**)&x2,    g_x2);
    cudaGetSymbolAddress((void**)&hb,    g_hb);

    cudaFuncSetAttribute(attn_mma_kernel,
                         cudaFuncAttributeMaxDynamicSharedMemorySize, ATT_SMEM_BYTES);

    ln_kernel<<<ROWS/8, 256>>>(x, emb, lng, lnb, qk_in, v_in);

    gemm_kernel<0><<<dim3(ROWS/64, 4), 256>>>(qk_in, Wqkv, bqkv, nullptr, nullptr,
                                              ROWS, 256, 128, qp, kp);
    gemm_kernel<1><<<dim3(ROWS/64, 2), 256>>>(v_in, Wqkv + 256*128, bqkv + 256,
                                              nullptr, nullptr, ROWS, 128, 128, vp, nullptr);

    attn_mma_kernel<<<dim3(S_/128, 16), 256, ATT_SMEM_BYTES>>>(qp, kp, vp, act, node, ctx);

    gemm_kernel<2><<<dim3(ROWS/64, 2), 256>>>(ctx, Wo, bo, x, x2,
                                              ROWS, 128, 128, nullptr, nullptr);
    gemm_kernel<3><<<dim3(ROWS/64, 4), 256>>>(x2, W1, b1, nullptr, hb,
                                              ROWS, 256, 128, nullptr, nullptr);
    gemm_kernel<2><<<dim3(ROWS/64, 2), 256>>>(hb, W2, b2, x2, out,
                                              ROWS, 128, 256, nullptr, nullptr);
}

// round 4
// speedup vs baseline: 4.0833x; 1.7404x over previous
#include <cuda_runtime.h>
#include <cuda_bf16.h>
#include <cstdint>

#define B_   8
#define S_   2048
#define D_   128
#define ROWS (B_*S_)            // 16384
#define QSCALE 0.18033688011112042f   // log2(e)/8

// ---------------- scratch (static device memory; no allocation) -------------
__device__ float g_qk_in[ROWS*D_];          // LN(x+emb)
__device__ float g_v_in [ROWS*D_];          // LN(x)
__device__ __nv_bfloat16 g_q[16*S_*64];     // (b,h,s,dh), pre-scaled by log2e/8
__device__ __nv_bfloat16 g_k[16*S_*64];     // (b,h,s,dh)
__device__ __nv_bfloat16 g_v[16*64*S_];     // (b,h,dh,s)
__device__ float g_ctx[ROWS*D_];            // (b,s,d)
__device__ float g_x2 [ROWS*D_];
__device__ float g_hb [ROWS*2*D_];

// ---------------- mma / cvt helpers -----------------------------------------
__device__ __forceinline__ uint32_t cvt_tf32(float f) {
    uint32_t u;
    asm("cvt.rna.tf32.f32 %0, %1;" : "=r"(u) : "f"(f));
    return u;
}
__device__ __forceinline__ uint32_t pack_bf16(float hi, float lo) {
    uint32_t d;
    asm("cvt.rn.bf16x2.f32 %0, %1, %2;" : "=r"(d) : "f"(hi), "f"(lo));
    return d;
}
__device__ __forceinline__ void mma_tf32(float* d, uint32_t a0, uint32_t a1,
                                         uint32_t a2, uint32_t a3,
                                         uint32_t b0, uint32_t b1) {
    asm volatile("mma.sync.aligned.m16n8k8.row.col.f32.tf32.tf32.f32 "
        "{%0,%1,%2,%3}, {%4,%5,%6,%7}, {%8,%9}, {%0,%1,%2,%3};"
        : "+f"(d[0]), "+f"(d[1]), "+f"(d[2]), "+f"(d[3])
        : "r"(a0), "r"(a1), "r"(a2), "r"(a3), "r"(b0), "r"(b1));
}
__device__ __forceinline__ void mma_bf16(float* d, uint32_t a0, uint32_t a1,
                                         uint32_t a2, uint32_t a3,
                                         uint32_t b0, uint32_t b1) {
    asm volatile("mma.sync.aligned.m16n8k16.row.col.f32.bf16.bf16.f32 "
        "{%0,%1,%2,%3}, {%4,%5,%6,%7}, {%8,%9}, {%0,%1,%2,%3};"
        : "+f"(d[0]), "+f"(d[1]), "+f"(d[2]), "+f"(d[3])
        : "r"(a0), "r"(a1), "r"(a2), "r"(a3), "r"(b0), "r"(b1));
}

// ---------------- fused dual LayerNorm --------------------------------------
__global__ void __launch_bounds__(256) ln_kernel(
    const float* __restrict__ x, const float* __restrict__ emb,
    const float* __restrict__ g, const float* __restrict__ bta,
    float* __restrict__ qk_in, float* __restrict__ v_in)
{
    int row  = blockIdx.x * 8 + (threadIdx.x >> 5);
    int lane = threadIdx.x & 31;
    size_t base = (size_t)row * 32 + lane;

    float4 xv = ((const float4*)x)[base];
    float4 ev = ((const float4*)emb)[base];
    float4 g4 = ((const float4*)g)[lane];
    float4 b4 = ((const float4*)bta)[lane];

    float4 t = make_float4(xv.x+ev.x, xv.y+ev.y, xv.z+ev.z, xv.w+ev.w);
    float s = t.x + t.y + t.z + t.w;
    #pragma unroll
    for (int o = 16; o; o >>= 1) s += __shfl_xor_sync(0xffffffffu, s, o);
    float mu = s * (1.0f/128.0f);
    float dx = t.x-mu, dy = t.y-mu, dz = t.z-mu, dw = t.w-mu;
    float v2 = dx*dx + dy*dy + dz*dz + dw*dw;
    #pragma unroll
    for (int o = 16; o; o >>= 1) v2 += __shfl_xor_sync(0xffffffffu, v2, o);
    float r = rsqrtf(v2 * (1.0f/128.0f) + 1e-5f);
    ((float4*)qk_in)[base] = make_float4(dx*r*g4.x + b4.x, dy*r*g4.y + b4.y,
                                         dz*r*g4.z + b4.z, dw*r*g4.w + b4.w);

    s = xv.x + xv.y + xv.z + xv.w;
    #pragma unroll
    for (int o = 16; o; o >>= 1) s += __shfl_xor_sync(0xffffffffu, s, o);
    mu = s * (1.0f/128.0f);
    dx = xv.x-mu; dy = xv.y-mu; dz = xv.z-mu; dw = xv.w-mu;
    v2 = dx*dx + dy*dy + dz*dz + dw*dw;
    #pragma unroll
    for (int o = 16; o; o >>= 1) v2 += __shfl_xor_sync(0xffffffffu, v2, o);
    r = rsqrtf(v2 * (1.0f/128.0f) + 1e-5f);
    ((float4*)v_in)[base] = make_float4(dx*r*g4.x + b4.x, dy*r*g4.y + b4.y,
                                        dz*r*g4.z + b4.z, dw*r*g4.w + b4.w);
}

// ================= tf32 tensor-core GEMM: C = A(MxK) * W(NxK)^T + bias ======
// CTA tile 128x128, k-chunk 32, 8 warps = 4x2, warp tile 32x64.
// MODE 0: scatter cols -> q (scaled, bf16) / k (bf16), layout (b,h,s,dh)
// MODE 1: scatter cols -> v (bf16), layout (b,h,dh,s)
// MODE 2: out[r,n] = addsrc[r,n] + val   (fp32)
// MODE 3: out[r,n] = 2*relu(val)         (fp32)
template<int MODE>
__global__ void __launch_bounds__(256, 2) gemm_tc(
    const float* __restrict__ A, const float* __restrict__ W,
    const float* __restrict__ bias, const float* __restrict__ addsrc,
    float* __restrict__ out, int N, int K,
    __nv_bfloat16* __restrict__ p0, __nv_bfloat16* __restrict__ p1)
{
    __shared__ uint32_t As[128*40];
    __shared__ uint32_t Ws[128*40];

    int m0 = blockIdx.x * 128, n0 = blockIdx.y * 128;
    int tid = threadIdx.x;
    int w = tid >> 5, lane = tid & 31, g = lane >> 2, tg = lane & 3;
    int wm = w >> 1, wn = w & 1;

    float c[2][8][4];
    #pragma unroll
    for (int mt = 0; mt < 2; mt++)
        #pragma unroll
        for (int j = 0; j < 8; j++)
            #pragma unroll
            for (int i = 0; i < 4; i++) c[mt][j][i] = 0.f;

    int fr = tid >> 1, hf = tid & 1;
    const float* Ar = A + (size_t)(m0 + fr) * K + 16*hf;
    const float* Wr = W + (size_t)(n0 + fr) * K + 16*hf;
    int sbase = fr*40 + hf*16;

    for (int kc = 0; kc < K; kc += 32) {
        __syncthreads();
        float4 a0 = *(const float4*)(Ar + kc),     a1 = *(const float4*)(Ar + kc + 4);
        float4 a2 = *(const float4*)(Ar + kc + 8), a3 = *(const float4*)(Ar + kc + 12);
        float4 w0 = *(const float4*)(Wr + kc),     w1 = *(const float4*)(Wr + kc + 4);
        float4 w2 = *(const float4*)(Wr + kc + 8), w3 = *(const float4*)(Wr + kc + 12);
        // pair-permuted store: pairs (k, k+4) adjacent
        *(uint2*)&As[sbase+0]  = make_uint2(cvt_tf32(a0.x), cvt_tf32(a1.x));
        *(uint2*)&As[sbase+2]  = make_uint2(cvt_tf32(a0.y), cvt_tf32(a1.y));
        *(uint2*)&As[sbase+4]  = make_uint2(cvt_tf32(a0.z), cvt_tf32(a1.z));
        *(uint2*)&As[sbase+6]  = make_uint2(cvt_tf32(a0.w), cvt_tf32(a1.w));
        *(uint2*)&As[sbase+8]  = make_uint2(cvt_tf32(a2.x), cvt_tf32(a3.x));
        *(uint2*)&As[sbase+10] = make_uint2(cvt_tf32(a2.y), cvt_tf32(a3.y));
        *(uint2*)&As[sbase+12] = make_uint2(cvt_tf32(a2.z), cvt_tf32(a3.z));
        *(uint2*)&As[sbase+14] = make_uint2(cvt_tf32(a2.w), cvt_tf32(a3.w));
        *(uint2*)&Ws[sbase+0]  = make_uint2(cvt_tf32(w0.x), cvt_tf32(w1.x));
        *(uint2*)&Ws[sbase+2]  = make_uint2(cvt_tf32(w0.y), cvt_tf32(w1.y));
        *(uint2*)&Ws[sbase+4]  = make_uint2(cvt_tf32(w0.z), cvt_tf32(w1.z));
        *(uint2*)&Ws[sbase+6]  = make_uint2(cvt_tf32(w0.w), cvt_tf32(w1.w));
        *(uint2*)&Ws[sbase+8]  = make_uint2(cvt_tf32(w2.x), cvt_tf32(w3.x));
        *(uint2*)&Ws[sbase+10] = make_uint2(cvt_tf32(w2.y), cvt_tf32(w3.y));
        *(uint2*)&Ws[sbase+12] = make_uint2(cvt_tf32(w2.z), cvt_tf32(w3.z));
        *(uint2*)&Ws[sbase+14] = make_uint2(cvt_tf32(w2.w), cvt_tf32(w3.w));
        __syncthreads();

        #pragma unroll
        for (int ks = 0; ks < 4; ks++) {
            uint2 bf[8];
            #pragma unroll
            for (int j = 0; j < 8; j++)
                bf[j] = *(const uint2*)&Ws[(64*wn + 8*j + g)*40 + ks*8 + 2*tg];
            #pragma unroll
            for (int mt = 0; mt < 2; mt++) {
                uint2 aa = *(const uint2*)&As[(32*wm + 16*mt + g)*40 + ks*8 + 2*tg];
                uint2 ab = *(const uint2*)&As[(32*wm + 16*mt + g + 8)*40 + ks*8 + 2*tg];
                #pragma unroll
                for (int j = 0; j < 8; j++)
                    mma_tf32(c[mt][j], aa.x, ab.x, aa.y, ab.y, bf[j].x, bf[j].y);
            }
        }
    }

    // ---- epilogue ----
    #pragma unroll
    for (int mt = 0; mt < 2; mt++) {
        int r0 = m0 + 32*wm + 16*mt + g;
        int r1 = r0 + 8;
        #pragma unroll
        for (int j = 0; j < 8; j++) {
            int n = n0 + 64*wn + 8*j + 2*tg;
            float2 bs = *(const float2*)(bias + n);
            float v00 = c[mt][j][0] + bs.x, v01 = c[mt][j][1] + bs.y;
            float v10 = c[mt][j][2] + bs.x, v11 = c[mt][j][3] + bs.y;
            if (MODE == 0) {
                if (n < 128) { v00 *= QSCALE; v01 *= QSCALE; v10 *= QSCALE; v11 *= QSCALE; }
                __nv_bfloat16* dst = (n < 128) ? p0 : p1;
                int e = n & 127, hh = e >> 6, dh = e & 63;
                int b0i = r0 >> 11, s0i = r0 & 2047;
                int b1i = r1 >> 11, s1i = r1 & 2047;
                *(uint32_t*)&dst[((size_t)(b0i*2 + hh)*2048 + s0i)*64 + dh] = pack_bf16(v01, v00);
                *(uint32_t*)&dst[((size_t)(b1i*2 + hh)*2048 + s1i)*64 + dh] = pack_bf16(v11, v10);
            } else if (MODE == 1) {
                int hh = n >> 6, dh = n & 63;
                int b0i = r0 >> 11, s0i = r0 & 2047;
                int b1i = r1 >> 11, s1i = r1 & 2047;
                p0[((size_t)(b0i*2 + hh)*64 + dh    )*2048 + s0i] = __float2bfloat16_rn(v00);
                p0[((size_t)(b0i*2 + hh)*64 + dh + 1)*2048 + s0i] = __float2bfloat16_rn(v01);
                p0[((size_t)(b1i*2 + hh)*64 + dh    )*2048 + s1i] = __float2bfloat16_rn(v10);
                p0[((size_t)(b1i*2 + hh)*64 + dh + 1)*2048 + s1i] = __float2bfloat16_rn(v11);
            } else if (MODE == 2) {
                float2 s0 = *(const float2*)(addsrc + (size_t)r0*N + n);
                float2 s1 = *(const float2*)(addsrc + (size_t)r1*N + n);
                *(float2*)(out + (size_t)r0*N + n) = make_float2(s0.x + v00, s0.y + v01);
                *(float2*)(out + (size_t)r1*N + n) = make_float2(s1.x + v10, s1.y + v11);
            } else {
                *(float2*)(out + (size_t)r0*N + n) =
                    make_float2(2.f*fmaxf(v00, 0.f), 2.f*fmaxf(v01, 0.f));
                *(float2*)(out + (size_t)r1*N + n) =
                    make_float2(2.f*fmaxf(v10, 0.f), 2.f*fmaxf(v11, 0.f));
            }
        }
    }
}

// ================= bf16 warp-mma flash attention =============================
// grid (S/128, B*H), 256 threads (8 warps). Q tile 128, K tile 64, DH=64.
// P = exp2(score) stays in registers (C-frag pairs == k16 A-frag pairs).
__global__ void __launch_bounds__(256, 2) attn_bf16_kernel(
    const __nv_bfloat16* __restrict__ q, const __nv_bfloat16* __restrict__ k,
    const __nv_bfloat16* __restrict__ v, const int* __restrict__ actions,
    const int* __restrict__ nodeT, float* __restrict__ ctx)
{
    __shared__ uint32_t Qs[128*40];   // [qrow][dh pairs, perm]
    __shared__ uint32_t Ks[64*40];    // [kcol][dh pairs, perm]
    __shared__ uint32_t Vs[64*40];    // [dh]  [kcol pairs, perm]
    __shared__ int2 mj[64];

    int tid = threadIdx.x;
    int w = tid >> 5, lane = tid & 31;
    int g = lane >> 2, tg = lane & 3;
    int bh = blockIdx.y, b = bh >> 1, h = bh & 1;
    int q0 = blockIdx.x * 128;

    // ---- Q tile fill (perm-paired) ----
    const uint4* qg = (const uint4*)(q + ((size_t)bh * S_ + q0) * 64);
    #pragma unroll
    for (int it = 0; it < 4; it++) {
        int i = tid + 256*it;
        int r = i >> 3, u4 = i & 7;          // uint4 index within row (8 per row)
        uint4 t = qg[r*8 + u4];
        int pb = r*40 + (u4 >> 1)*8 + (u4 & 1);
        Qs[pb + 0] = t.x; Qs[pb + 2] = t.y; Qs[pb + 4] = t.z; Qs[pb + 6] = t.w;
    }

    int rq0 = q0 + 16*w + g, rq1 = rq0 + 8;
    int mq0 = nodeT[rq0*3 + 2], jq0 = nodeT[rq0*3 + 0];
    int mq1 = nodeT[rq1*3 + 2], jq1 = nodeT[rq1*3 + 0];
    int aq0 = (actions[b*S_ + rq0] == 0);
    int aq1 = (actions[b*S_ + rq1] == 0);

    const uint4* kg = (const uint4*)(k + (size_t)bh * S_ * 64);
    const uint4* vg = (const uint4*)(v + (size_t)bh * 64 * S_);

    float o[8][4];
    #pragma unroll
    for (int j = 0; j < 8; j++)
        #pragma unroll
        for (int i = 0; i < 4; i++) o[j][i] = 0.f;
    float l0 = 0.f, l1 = 0.f;

    // prefetch registers: K/V tile fragments for this thread
    int fr = tid >> 2, fq = tid & 3;          // row 0..63, uint4 pair index
    uint4 pk0, pk1, pv0, pv1;
    {
        pk0 = kg[(size_t)fr*8 + fq*2];     pk1 = kg[(size_t)fr*8 + fq*2 + 1];
        pv0 = vg[(size_t)fr*256 + fq*2];   pv1 = vg[(size_t)fr*256 + fq*2 + 1];
    }

    for (int kt = 0; kt < 32; kt++) {
        int k0 = kt * 64;
        __syncthreads();   // previous tile fully consumed
        {
            int q40 = fq*2, q41 = fq*2 + 1;
            int pb0 = fr*40 + (q40 >> 1)*8 + (q40 & 1);
            int pb1 = fr*40 + (q41 >> 1)*8 + (q41 & 1);
            Ks[pb0+0] = pk0.x; Ks[pb0+2] = pk0.y; Ks[pb0+4] = pk0.z; Ks[pb0+6] = pk0.w;
            Ks[pb1+0] = pk1.x; Ks[pb1+2] = pk1.y; Ks[pb1+4] = pk1.z; Ks[pb1+6] = pk1.w;
            Vs[pb0+0] = pv0.x; Vs[pb0+2] = pv0.y; Vs[pb0+4] = pv0.z; Vs[pb0+6] = pv0.w;
            Vs[pb1+0] = pv1.x; Vs[pb1+2] = pv1.y; Vs[pb1+4] = pv1.z; Vs[pb1+6] = pv1.w;
        }
        if (tid < 64)
            mj[tid] = make_int2(nodeT[(k0+tid)*3 + 2], nodeT[(k0+tid)*3 + 0]);
        __syncthreads();

        if (kt < 31) {   // prefetch next tile (overlaps with compute)
            int kn = k0 + 64;
            pk0 = kg[(size_t)(kn + fr)*8 + fq*2];
            pk1 = kg[(size_t)(kn + fr)*8 + fq*2 + 1];
            pv0 = vg[(size_t)fr*256 + (kn >> 3) + fq*2];
            pv1 = vg[(size_t)fr*256 + (kn >> 3) + fq*2 + 1];
        }

        // ---- S = Q K^T  (128x64, contraction dh=64 -> 4 k16 steps) ----
        float c[8][4];
        #pragma unroll
        for (int j = 0; j < 8; j++)
            #pragma unroll
            for (int i = 0; i < 4; i++) c[j][i] = 0.f;
        #pragma unroll
        for (int ks = 0; ks < 4; ks++) {
            uint2 qa = *(const uint2*)&Qs[(16*w + g)*40 + ks*8 + 2*tg];
            uint2 qb = *(const uint2*)&Qs[(16*w + g + 8)*40 + ks*8 + 2*tg];
            #pragma unroll
            for (int j = 0; j < 8; j++) {
                uint2 kb = *(const uint2*)&Ks[(8*j + g)*40 + ks*8 + 2*tg];
                mma_bf16(c[j], qa.x, qb.x, qa.y, qb.y, kb.x, kb.y);
            }
        }

        // ---- masked exp (unnormalized) ----
        #pragma unroll
        for (int j = 0; j < 8; j++) {
            int c0 = 8*j + 2*tg, c1 = c0 + 1;
            int2 m0 = mj[c0], m1 = mj[c1];
            float e00, e01, e10, e11;
            asm("ex2.approx.f32 %0, %1;" : "=f"(e00) : "f"(c[j][0]));
            asm("ex2.approx.f32 %0, %1;" : "=f"(e01) : "f"(c[j][1]));
            asm("ex2.approx.f32 %0, %1;" : "=f"(e10) : "f"(c[j][2]));
            asm("ex2.approx.f32 %0, %1;" : "=f"(e11) : "f"(c[j][3]));
            if (aq0 & (mq0 != m0.x) & (jq0 != m0.y)) e00 = 0.f;
            if (aq0 & (mq0 != m1.x) & (jq0 != m1.y)) e01 = 0.f;
            if (aq1 & (mq1 != m0.x) & (jq1 != m0.y)) e10 = 0.f;
            if (aq1 & (mq1 != m1.x) & (jq1 != m1.y)) e11 = 0.f;
            c[j][0] = e00; c[j][1] = e01; c[j][2] = e10; c[j][3] = e11;
            l0 += e00 + e01;
            l1 += e10 + e11;
        }

        // ---- O += P V : P refragmented in registers (no smem!) ----
        #pragma unroll
        for (int ks = 0; ks < 4; ks++) {
            uint32_t a0 = pack_bf16(c[2*ks  ][1], c[2*ks  ][0]);
            uint32_t a1 = pack_bf16(c[2*ks  ][3], c[2*ks  ][2]);
            uint32_t a2 = pack_bf16(c[2*ks+1][1], c[2*ks+1][0]);
            uint32_t a3 = pack_bf16(c[2*ks+1][3], c[2*ks+1][2]);
            #pragma unroll
            for (int j = 0; j < 8; j++) {
                uint2 vb = *(const uint2*)&Vs[(8*j + g)*40 + ks*8 + 2*tg];
                mma_bf16(o[j], a0, a1, a2, a3, vb.x, vb.y);
            }
        }
    }

    // ---- reduce l over quad, normalize, write ----
    #pragma unroll
    for (int off = 1; off < 4; off <<= 1) {
        l0 += __shfl_xor_sync(0xffffffffu, l0, off);
        l1 += __shfl_xor_sync(0xffffffffu, l1, off);
    }
    float inv0 = 1.0f / l0, inv1 = 1.0f / l1;

    float* og0 = ctx + ((size_t)b*S_ + rq0)*128 + h*64;
    float* og1 = ctx + ((size_t)b*S_ + rq1)*128 + h*64;
    #pragma unroll
    for (int j = 0; j < 8; j++) {
        int c0 = 8*j + 2*tg;
        *(float2*)(og0 + c0) = make_float2(o[j][0]*inv0, o[j][1]*inv0);
        *(float2*)(og1 + c0) = make_float2(o[j][2]*inv1, o[j][3]*inv1);
    }
}

// ---------------- launcher ---------------------------------------------------
extern "C" void kernel_launch(void* const* d_in, const int* in_sizes, int n_in,
                              void* d_out, int out_size)
{
    const float* x    = (const float*)d_in[0];
    const float* emb  = (const float*)d_in[1];
    const int*   act  = (const int*)  d_in[2];
    const int*   node = (const int*)  d_in[3];
    const float* Wqkv = (const float*)d_in[4];
    const float* bqkv = (const float*)d_in[5];
    const float* Wo   = (const float*)d_in[6];
    const float* bo   = (const float*)d_in[7];
    const float* lng  = (const float*)d_in[8];
    const float* lnb  = (const float*)d_in[9];
    const float* W1   = (const float*)d_in[10];
    const float* b1   = (const float*)d_in[11];
    const float* W2   = (const float*)d_in[12];
    const float* b2   = (const float*)d_in[13];
    float* out = (float*)d_out;

    float *qk_in, *v_in, *ctx, *x2, *hb;
    __nv_bfloat16 *qp, *kp, *vp;
    cudaGetSymbolAddress((void**)&qk_in, g_qk_in);
    cudaGetSymbolAddress((void**)&v_in,  g_v_in);
    cudaGetSymbolAddress((void**)&qp,    g_q);
    cudaGetSymbolAddress((void**)&kp,    g_k);
    cudaGetSymbolAddress((void**)&vp,    g_v);
    cudaGetSymbolAddress((void**)&ctx,   g_ctx);
    cudaGetSymbolAddress((void**)&x2,    g_x2);
    cudaGetSymbolAddress((void**)&hb,    g_hb);

    ln_kernel<<<ROWS/8, 256>>>(x, emb, lng, lnb, qk_in, v_in);

    // QK projection -> q (scaled bf16), k (bf16)
    gemm_tc<0><<<dim3(ROWS/128, 2), 256>>>(qk_in, Wqkv, bqkv, nullptr, nullptr,
                                           256, 128, qp, kp);
    // V projection -> v (bf16, transposed)
    gemm_tc<1><<<dim3(ROWS/128, 1), 256>>>(v_in, Wqkv + 256*128, bqkv + 256,
                                           nullptr, nullptr, 128, 128, vp, nullptr);

    attn_bf16_kernel<<<dim3(S_/128, 16), 256>>>(qp, kp, vp, act, node, ctx);

    // out projection + residual
    gemm_tc<2><<<dim3(ROWS/128, 1), 256>>>(ctx, Wo, bo, x, x2,
                                           128, 128, nullptr, nullptr);
    // FFN1
    gemm_tc<3><<<dim3(ROWS/128, 2), 256>>>(x2, W1, b1, nullptr, hb,
                                           256, 128, nullptr, nullptr);
    // FFN2 + residual
    gemm_tc<2><<<dim3(ROWS/128, 1), 256>>>(hb, W2, b2, x2, out,
                                           128, 256, nullptr, nullptr);
}

// round 5
// speedup vs baseline: 4.7193x; 1.1558x over previous
#include <cuda_runtime.h>
#include <cuda_bf16.h>
#include <cstdint>

#define B_   8
#define S_   2048
#define D_   128
#define ROWS (B_*S_)            // 16384
#define QSCALE 0.18033688011112042f   // log2(e)/8

// ---------------- scratch (static device memory; no allocation) -------------
__device__ float g_qk_in[ROWS*D_];          // LN(x+emb)
__device__ float g_v_in [ROWS*D_];          // LN(x)
__device__ __nv_bfloat16 g_q[16*S_*64];     // (b,h,s,dh), pre-scaled by log2e/8
__device__ __nv_bfloat16 g_k[16*S_*64];     // (b,h,s,dh)
__device__ __nv_bfloat16 g_v[16*64*S_];     // (b,h,dh,s)
__device__ float g_ctx[ROWS*D_];            // (b,s,d)
__device__ float g_x2 [ROWS*D_];
__device__ float g_hb [ROWS*2*D_];

// ---------------- helpers ----------------------------------------------------
__device__ __forceinline__ uint32_t cvt_tf32(float f) {
    uint32_t u;
    asm("cvt.rna.tf32.f32 %0, %1;" : "=r"(u) : "f"(f));
    return u;
}
__device__ __forceinline__ uint32_t pack_bf16(float hi, float lo) {
    uint32_t d;
    asm("cvt.rn.bf16x2.f32 %0, %1, %2;" : "=r"(d) : "f"(hi), "f"(lo));
    return d;
}
__device__ __forceinline__ void mma_tf32(float* d, uint32_t a0, uint32_t a1,
                                         uint32_t a2, uint32_t a3,
                                         uint32_t b0, uint32_t b1) {
    asm volatile("mma.sync.aligned.m16n8k8.row.col.f32.tf32.tf32.f32 "
        "{%0,%1,%2,%3}, {%4,%5,%6,%7}, {%8,%9}, {%0,%1,%2,%3};"
        : "+f"(d[0]), "+f"(d[1]), "+f"(d[2]), "+f"(d[3])
        : "r"(a0), "r"(a1), "r"(a2), "r"(a3), "r"(b0), "r"(b1));
}
__device__ __forceinline__ void mma_bf16(float* d, uint32_t a0, uint32_t a1,
                                         uint32_t a2, uint32_t a3,
                                         uint32_t b0, uint32_t b1) {
    asm volatile("mma.sync.aligned.m16n8k16.row.col.f32.bf16.bf16.f32 "
        "{%0,%1,%2,%3}, {%4,%5,%6,%7}, {%8,%9}, {%0,%1,%2,%3};"
        : "+f"(d[0]), "+f"(d[1]), "+f"(d[2]), "+f"(d[3])
        : "r"(a0), "r"(a1), "r"(a2), "r"(a3), "r"(b0), "r"(b1));
}
__device__ __forceinline__ void ldsm4(uint32_t& r0, uint32_t& r1,
                                      uint32_t& r2, uint32_t& r3,
                                      const void* p) {
    uint32_t a = (uint32_t)__cvta_generic_to_shared(p);
    asm volatile("ldmatrix.sync.aligned.m8n8.x4.shared.b16 {%0,%1,%2,%3}, [%4];"
        : "=r"(r0), "=r"(r1), "=r"(r2), "=r"(r3) : "r"(a));
}

// ---------------- fused dual LayerNorm --------------------------------------
__global__ void __launch_bounds__(256) ln_kernel(
    const float* __restrict__ x, const float* __restrict__ emb,
    const float* __restrict__ g, const float* __restrict__ bta,
    float* __restrict__ qk_in, float* __restrict__ v_in)
{
    int row  = blockIdx.x * 8 + (threadIdx.x >> 5);
    int lane = threadIdx.x & 31;
    size_t base = (size_t)row * 32 + lane;

    float4 xv = ((const float4*)x)[base];
    float4 ev = ((const float4*)emb)[base];
    float4 g4 = ((const float4*)g)[lane];
    float4 b4 = ((const float4*)bta)[lane];

    float4 t = make_float4(xv.x+ev.x, xv.y+ev.y, xv.z+ev.z, xv.w+ev.w);
    float s = t.x + t.y + t.z + t.w;
    #pragma unroll
    for (int o = 16; o; o >>= 1) s += __shfl_xor_sync(0xffffffffu, s, o);
    float mu = s * (1.0f/128.0f);
    float dx = t.x-mu, dy = t.y-mu, dz = t.z-mu, dw = t.w-mu;
    float v2 = dx*dx + dy*dy + dz*dz + dw*dw;
    #pragma unroll
    for (int o = 16; o; o >>= 1) v2 += __shfl_xor_sync(0xffffffffu, v2, o);
    float r = rsqrtf(v2 * (1.0f/128.0f) + 1e-5f);
    ((float4*)qk_in)[base] = make_float4(dx*r*g4.x + b4.x, dy*r*g4.y + b4.y,
                                         dz*r*g4.z + b4.z, dw*r*g4.w + b4.w);

    s = xv.x + xv.y + xv.z + xv.w;
    #pragma unroll
    for (int o = 16; o; o >>= 1) s += __shfl_xor_sync(0xffffffffu, s, o);
    mu = s * (1.0f/128.0f);
    dx = xv.x-mu; dy = xv.y-mu; dz = xv.z-mu; dw = xv.w-mu;
    v2 = dx*dx + dy*dy + dz*dz + dw*dw;
    #pragma unroll
    for (int o = 16; o; o >>= 1) v2 += __shfl_xor_sync(0xffffffffu, v2, o);
    r = rsqrtf(v2 * (1.0f/128.0f) + 1e-5f);
    ((float4*)v_in)[base] = make_float4(dx*r*g4.x + b4.x, dy*r*g4.y + b4.y,
                                        dz*r*g4.z + b4.z, dw*r*g4.w + b4.w);
}

// ================= tf32 tensor-core GEMM: C = A(MxK) * W(NxK)^T + bias ======
// CTA tile 128x128, k-chunk 32, 8 warps = 4x2, warp tile 32x64.
template<int MODE>
__global__ void __launch_bounds__(256, 2) gemm_tc(
    const float* __restrict__ A, const float* __restrict__ W,
    const float* __restrict__ bias, const float* __restrict__ addsrc,
    float* __restrict__ out, int N, int K,
    __nv_bfloat16* __restrict__ p0, __nv_bfloat16* __restrict__ p1)
{
    __shared__ uint32_t As[128*40];
    __shared__ uint32_t Ws[128*40];

    int m0 = blockIdx.x * 128, n0 = blockIdx.y * 128;
    int tid = threadIdx.x;
    int w = tid >> 5, lane = tid & 31, g = lane >> 2, tg = lane & 3;
    int wm = w >> 1, wn = w & 1;

    float c[2][8][4];
    #pragma unroll
    for (int mt = 0; mt < 2; mt++)
        #pragma unroll
        for (int j = 0; j < 8; j++)
            #pragma unroll
            for (int i = 0; i < 4; i++) c[mt][j][i] = 0.f;

    int fr = tid >> 1, hf = tid & 1;
    const float* Ar = A + (size_t)(m0 + fr) * K + 16*hf;
    const float* Wr = W + (size_t)(n0 + fr) * K + 16*hf;
    int sbase = fr*40 + hf*16;

    for (int kc = 0; kc < K; kc += 32) {
        __syncthreads();
        float4 a0 = *(const float4*)(Ar + kc),     a1 = *(const float4*)(Ar + kc + 4);
        float4 a2 = *(const float4*)(Ar + kc + 8), a3 = *(const float4*)(Ar + kc + 12);
        float4 w0 = *(const float4*)(Wr + kc),     w1 = *(const float4*)(Wr + kc + 4);
        float4 w2 = *(const float4*)(Wr + kc + 8), w3 = *(const float4*)(Wr + kc + 12);
        *(uint2*)&As[sbase+0]  = make_uint2(cvt_tf32(a0.x), cvt_tf32(a1.x));
        *(uint2*)&As[sbase+2]  = make_uint2(cvt_tf32(a0.y), cvt_tf32(a1.y));
        *(uint2*)&As[sbase+4]  = make_uint2(cvt_tf32(a0.z), cvt_tf32(a1.z));
        *(uint2*)&As[sbase+6]  = make_uint2(cvt_tf32(a0.w), cvt_tf32(a1.w));
        *(uint2*)&As[sbase+8]  = make_uint2(cvt_tf32(a2.x), cvt_tf32(a3.x));
        *(uint2*)&As[sbase+10] = make_uint2(cvt_tf32(a2.y), cvt_tf32(a3.y));
        *(uint2*)&As[sbase+12] = make_uint2(cvt_tf32(a2.z), cvt_tf32(a3.z));
        *(uint2*)&As[sbase+14] = make_uint2(cvt_tf32(a2.w), cvt_tf32(a3.w));
        *(uint2*)&Ws[sbase+0]  = make_uint2(cvt_tf32(w0.x), cvt_tf32(w1.x));
        *(uint2*)&Ws[sbase+2]  = make_uint2(cvt_tf32(w0.y), cvt_tf32(w1.y));
        *(uint2*)&Ws[sbase+4]  = make_uint2(cvt_tf32(w0.z), cvt_tf32(w1.z));
        *(uint2*)&Ws[sbase+6]  = make_uint2(cvt_tf32(w0.w), cvt_tf32(w1.w));
        *(uint2*)&Ws[sbase+8]  = make_uint2(cvt_tf32(w2.x), cvt_tf32(w3.x));
        *(uint2*)&Ws[sbase+10] = make_uint2(cvt_tf32(w2.y), cvt_tf32(w3.y));
        *(uint2*)&Ws[sbase+12] = make_uint2(cvt_tf32(w2.z), cvt_tf32(w3.z));
        *(uint2*)&Ws[sbase+14] = make_uint2(cvt_tf32(w2.w), cvt_tf32(w3.w));
        __syncthreads();

        #pragma unroll
        for (int ks = 0; ks < 4; ks++) {
            uint2 bf[8];
            #pragma unroll
            for (int j = 0; j < 8; j++)
                bf[j] = *(const uint2*)&Ws[(64*wn + 8*j + g)*40 + ks*8 + 2*tg];
            #pragma unroll
            for (int mt = 0; mt < 2; mt++) {
                uint2 aa = *(const uint2*)&As[(32*wm + 16*mt + g)*40 + ks*8 + 2*tg];
                uint2 ab = *(const uint2*)&As[(32*wm + 16*mt + g + 8)*40 + ks*8 + 2*tg];
                #pragma unroll
                for (int j = 0; j < 8; j++)
                    mma_tf32(c[mt][j], aa.x, ab.x, aa.y, ab.y, bf[j].x, bf[j].y);
            }
        }
    }

    #pragma unroll
    for (int mt = 0; mt < 2; mt++) {
        int r0 = m0 + 32*wm + 16*mt + g;
        int r1 = r0 + 8;
        #pragma unroll
        for (int j = 0; j < 8; j++) {
            int n = n0 + 64*wn + 8*j + 2*tg;
            float2 bs = *(const float2*)(bias + n);
            float v00 = c[mt][j][0] + bs.x, v01 = c[mt][j][1] + bs.y;
            float v10 = c[mt][j][2] + bs.x, v11 = c[mt][j][3] + bs.y;
            if (MODE == 0) {
                if (n < 128) { v00 *= QSCALE; v01 *= QSCALE; v10 *= QSCALE; v11 *= QSCALE; }
                __nv_bfloat16* dst = (n < 128) ? p0 : p1;
                int e = n & 127, hh = e >> 6, dh = e & 63;
                int b0i = r0 >> 11, s0i = r0 & 2047;
                int b1i = r1 >> 11, s1i = r1 & 2047;
                *(uint32_t*)&dst[((size_t)(b0i*2 + hh)*2048 + s0i)*64 + dh] = pack_bf16(v01, v00);
                *(uint32_t*)&dst[((size_t)(b1i*2 + hh)*2048 + s1i)*64 + dh] = pack_bf16(v11, v10);
            } else if (MODE == 1) {
                int hh = n >> 6, dh = n & 63;
                int b0i = r0 >> 11, s0i = r0 & 2047;
                int b1i = r1 >> 11, s1i = r1 & 2047;
                p0[((size_t)(b0i*2 + hh)*64 + dh    )*2048 + s0i] = __float2bfloat16_rn(v00);
                p0[((size_t)(b0i*2 + hh)*64 + dh + 1)*2048 + s0i] = __float2bfloat16_rn(v01);
                p0[((size_t)(b1i*2 + hh)*64 + dh    )*2048 + s1i] = __float2bfloat16_rn(v10);
                p0[((size_t)(b1i*2 + hh)*64 + dh + 1)*2048 + s1i] = __float2bfloat16_rn(v11);
            } else if (MODE == 2) {
                float2 s0 = *(const float2*)(addsrc + (size_t)r0*N + n);
                float2 s1 = *(const float2*)(addsrc + (size_t)r1*N + n);
                *(float2*)(out + (size_t)r0*N + n) = make_float2(s0.x + v00, s0.y + v01);
                *(float2*)(out + (size_t)r1*N + n) = make_float2(s1.x + v10, s1.y + v11);
            } else {
                *(float2*)(out + (size_t)r0*N + n) =
                    make_float2(2.f*fmaxf(v00, 0.f), 2.f*fmaxf(v01, 0.f));
                *(float2*)(out + (size_t)r1*N + n) =
                    make_float2(2.f*fmaxf(v10, 0.f), 2.f*fmaxf(v11, 0.f));
            }
        }
    }
}

// ================= bf16 ldmatrix flash attention =============================
// grid (S/128, B*H), 256 threads (8 warps). Q tile 128, K tile 64, DH=64.
// Swizzled row-major b16 tiles: row = 128B (8 chunks of 16B), chunk c stored at
// c ^ (row & 7). Fragment loads via ldmatrix.x4; P stays in registers.
__global__ void __launch_bounds__(256, 2) attn_bf16_kernel(
    const __nv_bfloat16* __restrict__ q, const __nv_bfloat16* __restrict__ k,
    const __nv_bfloat16* __restrict__ v, const int* __restrict__ actions,
    const int* __restrict__ nodeT, float* __restrict__ ctx)
{
    __shared__ uint4 Qs[1024];   // 128 rows x 128B  (q rows x dh)
    __shared__ uint4 Ks[512];    // 64 rows  x 128B  (kcol x dh)
    __shared__ uint4 Vs[512];    // 64 rows  x 128B  (dh x kcol)
    __shared__ int2  mj[64];

    int tid = threadIdx.x;
    int w = tid >> 5, lane = tid & 31;
    int g = lane >> 2, tg = lane & 3;
    int bh = blockIdx.y, b = bh >> 1, h = bh & 1;
    int q0 = blockIdx.x * 128;

    // ---- Q tile fill (swizzled STS.128) ----
    const uint4* qg = (const uint4*)(q + ((size_t)bh * S_ + q0) * 64);
    #pragma unroll
    for (int it = 0; it < 4; it++) {
        int i = tid + 256*it;
        int r = i >> 3, cc = i & 7;
        Qs[r*8 + (cc ^ (r & 7))] = qg[i];
    }

    int rq0 = q0 + 16*w + g, rq1 = rq0 + 8;
    int mq0 = nodeT[rq0*3 + 2], jq0 = nodeT[rq0*3 + 0];
    int mq1 = nodeT[rq1*3 + 2], jq1 = nodeT[rq1*3 + 0];
    int aq0 = (actions[b*S_ + rq0] == 0);
    int aq1 = (actions[b*S_ + rq1] == 0);

    const uint4* kg = (const uint4*)(k + (size_t)bh * S_ * 64);
    const uint4* vg = (const uint4*)(v + (size_t)bh * 64 * S_);

    float o[8][4];
    #pragma unroll
    for (int j = 0; j < 8; j++)
        #pragma unroll
        for (int i = 0; i < 4; i++) o[j][i] = 0.f;
    float l0 = 0.f, l1 = 0.f;

    // fill mapping: row fr (0..63), chunks 2*fq, 2*fq+1 (swizzled)
    int fr = tid >> 2, fq = tid & 3;
    int st0 = fr*8 + ((2*fq)   ^ (fr & 7));
    int st1 = fr*8 + ((2*fq+1) ^ (fr & 7));

    // fragment lane geometry
    int rowq = 16*w + (lane & 7) + 8*((lane >> 3) & 1);
    int cbq  = lane >> 4;                 // Q: chunk = 2*ks + cbq
    int xq   = rowq & 7;
    const uint4* aqrow = Qs + rowq*8;

    int rowk = (lane & 7) + 8*(lane >> 4);   // +16*J per j-pair
    int cbk  = (lane >> 3) & 1;              // K/V: chunk = 2*ks + cbk
    int xk   = rowk & 7;
    const uint4* akrow = Ks + rowk*8;
    const uint4* avrow = Vs + rowk*8;

    uint4 pk0 = kg[(size_t)fr*8 + fq*2],     pk1 = kg[(size_t)fr*8 + fq*2 + 1];
    uint4 pv0 = vg[(size_t)fr*256 + fq*2],   pv1 = vg[(size_t)fr*256 + fq*2 + 1];

    for (int kt = 0; kt < 32; kt++) {
        int k0 = kt * 64;
        __syncthreads();   // previous tile fully consumed
        Ks[st0] = pk0; Ks[st1] = pk1;
        Vs[st0] = pv0; Vs[st1] = pv1;
        if (tid < 64)
            mj[tid] = make_int2(nodeT[(k0+tid)*3 + 2], nodeT[(k0+tid)*3 + 0]);
        __syncthreads();

        if (kt < 31) {
            int kn = k0 + 64;
            pk0 = kg[(size_t)(kn + fr)*8 + fq*2];
            pk1 = kg[(size_t)(kn + fr)*8 + fq*2 + 1];
            pv0 = vg[(size_t)fr*256 + (kn >> 3) + fq*2];
            pv1 = vg[(size_t)fr*256 + (kn >> 3) + fq*2 + 1];
        }

        // ---- S = Q K^T (128x64, dh=64 -> 4 k16 steps) ----
        float c[8][4];
        #pragma unroll
        for (int j = 0; j < 8; j++)
            #pragma unroll
            for (int i = 0; i < 4; i++) c[j][i] = 0.f;
        #pragma unroll
        for (int ks = 0; ks < 4; ks++) {
            uint32_t qa0, qa1, qa2, qa3;
            ldsm4(qa0, qa1, qa2, qa3, aqrow + ((2*ks + cbq) ^ xq));
            int ck = (2*ks + cbk) ^ xk;
            #pragma unroll
            for (int J = 0; J < 4; J++) {
                uint32_t b0, b1, b2, b3;
                ldsm4(b0, b1, b2, b3, akrow + J*128 + ck);
                mma_bf16(c[2*J],   qa0, qa1, qa2, qa3, b0, b1);
                mma_bf16(c[2*J+1], qa0, qa1, qa2, qa3, b2, b3);
            }
        }

        // ---- masked exp (unnormalized) ----
        #pragma unroll
        for (int j = 0; j < 8; j++) {
            int c0 = 8*j + 2*tg, c1 = c0 + 1;
            int2 m0 = mj[c0], m1 = mj[c1];
            float e00, e01, e10, e11;
            asm("ex2.approx.f32 %0, %1;" : "=f"(e00) : "f"(c[j][0]));
            asm("ex2.approx.f32 %0, %1;" : "=f"(e01) : "f"(c[j][1]));
            asm("ex2.approx.f32 %0, %1;" : "=f"(e10) : "f"(c[j][2]));
            asm("ex2.approx.f32 %0, %1;" : "=f"(e11) : "f"(c[j][3]));
            if (aq0 & (mq0 != m0.x) & (jq0 != m0.y)) e00 = 0.f;
            if (aq0 & (mq0 != m1.x) & (jq0 != m1.y)) e01 = 0.f;
            if (aq1 & (mq1 != m0.x) & (jq1 != m0.y)) e10 = 0.f;
            if (aq1 & (mq1 != m1.x) & (jq1 != m1.y)) e11 = 0.f;
            c[j][0] = e00; c[j][1] = e01; c[j][2] = e10; c[j][3] = e11;
            l0 += e00 + e01;
            l1 += e10 + e11;
        }

        // ---- O += P V (P refragmented in registers, no smem) ----
        #pragma unroll
        for (int ks = 0; ks < 4; ks++) {
            uint32_t a0 = pack_bf16(c[2*ks  ][1], c[2*ks  ][0]);
            uint32_t a1 = pack_bf16(c[2*ks  ][3], c[2*ks  ][2]);
            uint32_t a2 = pack_bf16(c[2*ks+1][1], c[2*ks+1][0]);
            uint32_t a3 = pack_bf16(c[2*ks+1][3], c[2*ks+1][2]);
            int cv = (2*ks + cbk) ^ xk;
            #pragma unroll
            for (int J = 0; J < 4; J++) {
                uint32_t b0, b1, b2, b3;
                ldsm4(b0, b1, b2, b3, avrow + J*128 + cv);
                mma_bf16(o[2*J],   a0, a1, a2, a3, b0, b1);
                mma_bf16(o[2*J+1], a0, a1, a2, a3, b2, b3);
            }
        }
    }

    #pragma unroll
    for (int off = 1; off < 4; off <<= 1) {
        l0 += __shfl_xor_sync(0xffffffffu, l0, off);
        l1 += __shfl_xor_sync(0xffffffffu, l1, off);
    }
    float inv0 = 1.0f / l0, inv1 = 1.0f / l1;

    float* og0 = ctx + ((size_t)b*S_ + rq0)*128 + h*64;
    float* og1 = ctx + ((size_t)b*S_ + rq1)*128 + h*64;
    #pragma unroll
    for (int j = 0; j < 8; j++) {
        int c0 = 8*j + 2*tg;
        *(float2*)(og0 + c0) = make_float2(o[j][0]*inv0, o[j][1]*inv0);
        *(float2*)(og1 + c0) = make_float2(o[j][2]*inv1, o[j][3]*inv1);
    }
}

// ---------------- launcher ---------------------------------------------------
extern "C" void kernel_launch(void* const* d_in, const int* in_sizes, int n_in,
                              void* d_out, int out_size)
{
    const float* x    = (const float*)d_in[0];
    const float* emb  = (const float*)d_in[1];
    const int*   act  = (const int*)  d_in[2];
    const int*   node = (const int*)  d_in[3];
    const float* Wqkv = (const float*)d_in[4];
    const float* bqkv = (const float*)d_in[5];
    const float* Wo   = (const float*)d_in[6];
    const float* bo   = (const float*)d_in[7];
    const float* lng  = (const float*)d_in[8];
    const float* lnb  = (const float*)d_in[9];
    const float* W1   = (const float*)d_in[10];
    const float* b1   = (const float*)d_in[11];
    const float* W2   = (const float*)d_in[12];
    const float* b2   = (const float*)d_in[13];
    float* out = (float*)d_out;

    float *qk_in, *v_in, *ctx, *x2, *hb;
    __nv_bfloat16 *qp, *kp, *vp;
    cudaGetSymbolAddress((void**)&qk_in, g_qk_in);
    cudaGetSymbolAddress((void**)&v_in,  g_v_in);
    cudaGetSymbolAddress((void**)&qp,    g_q);
    cudaGetSymbolAddress((void**)&kp,    g_k);
    cudaGetSymbolAddress((void**)&vp,    g_v);
    cudaGetSymbolAddress((void**)&ctx,   g_ctx);
    cudaGetSymbolAddress((void**)&x2,    g_x2);
    cudaGetSymbolAddress((void**)&hb,    g_hb);

    ln_kernel<<<ROWS/8, 256>>>(x, emb, lng, lnb, qk_in, v_in);

    gemm_tc<0><<<dim3(ROWS/128, 2), 256>>>(qk_in, Wqkv, bqkv, nullptr, nullptr,
                                           256, 128, qp, kp);
    gemm_tc<1><<<dim3(ROWS/128, 1), 256>>>(v_in, Wqkv + 256*128, bqkv + 256,
                                           nullptr, nullptr, 128, 128, vp, nullptr);

    attn_bf16_kernel<<<dim3(S_/128, 16), 256>>>(qp, kp, vp, act, node, ctx);

    gemm_tc<2><<<dim3(ROWS/128, 1), 256>>>(ctx, Wo, bo, x, x2,
                                           128, 128, nullptr, nullptr);
    gemm_tc<3><<<dim3(ROWS/128, 2), 256>>>(x2, W1, b1, nullptr, hb,
                                           256, 128, nullptr, nullptr);
    gemm_tc<2><<<dim3(ROWS/128, 1), 256>>>(hb, W2, b2, x2, out,
                                           128, 256, nullptr, nullptr);
}

// round 6
// speedup vs baseline: 5.0256x; 1.0649x over previous
#include <cuda_runtime.h>
#include <cuda_fp16.h>
#include <cstdint>

#define B_   8
#define S_   2048
#define D_   128
#define ROWS (B_*S_)            // 16384
#define QSCALE 0.18033688011112042f   // log2(e)/8

// ---------------- scratch (static device memory; no allocation) -------------
__device__ float g_qk_in[ROWS*D_];          // LN(x+emb)
__device__ float g_v_in [ROWS*D_];          // LN(x)
__device__ __half g_q[16*S_*64];            // (b,h,s,dh), pre-scaled by log2e/8
__device__ __half g_k[16*S_*64];            // (b,h,s,dh)
__device__ __half g_v[16*64*S_];            // (b,h,dh,s)
__device__ float g_ctx[ROWS*D_];            // (b,s,d)
__device__ float g_x2 [ROWS*D_];
__device__ float g_hb [ROWS*2*D_];
__device__ uint32_t g_mask[S_*64];          // pair mask bits: [q][k>>5] bit (k&31)

// ---------------- helpers ----------------------------------------------------
__device__ __forceinline__ uint32_t cvt_tf32(float f) {
    uint32_t u;
    asm("cvt.rna.tf32.f32 %0, %1;" : "=r"(u) : "f"(f));
    return u;
}
__device__ __forceinline__ uint32_t pack_f16(float hi, float lo) {
    uint32_t d;
    asm("cvt.rn.f16x2.f32 %0, %1, %2;" : "=r"(d) : "f"(hi), "f"(lo));
    return d;
}
__device__ __forceinline__ uint32_t ex2h2(uint32_t x) {
    asm("ex2.approx.f16x2 %0, %0;" : "+r"(x));
    return x;
}
__device__ __forceinline__ void mma_tf32(float* d, uint32_t a0, uint32_t a1,
                                         uint32_t a2, uint32_t a3,
                                         uint32_t b0, uint32_t b1) {
    asm volatile("mma.sync.aligned.m16n8k8.row.col.f32.tf32.tf32.f32 "
        "{%0,%1,%2,%3}, {%4,%5,%6,%7}, {%8,%9}, {%0,%1,%2,%3};"
        : "+f"(d[0]), "+f"(d[1]), "+f"(d[2]), "+f"(d[3])
        : "r"(a0), "r"(a1), "r"(a2), "r"(a3), "r"(b0), "r"(b1));
}
__device__ __forceinline__ void mma_f16(float* d, uint32_t a0, uint32_t a1,
                                        uint32_t a2, uint32_t a3,
                                        uint32_t b0, uint32_t b1) {
    asm volatile("mma.sync.aligned.m16n8k16.row.col.f32.f16.f16.f32 "
        "{%0,%1,%2,%3}, {%4,%5,%6,%7}, {%8,%9}, {%0,%1,%2,%3};"
        : "+f"(d[0]), "+f"(d[1]), "+f"(d[2]), "+f"(d[3])
        : "r"(a0), "r"(a1), "r"(a2), "r"(a3), "r"(b0), "r"(b1));
}
__device__ __forceinline__ void ldsm4(uint32_t& r0, uint32_t& r1,
                                      uint32_t& r2, uint32_t& r3,
                                      const void* p) {
    uint32_t a = (uint32_t)__cvta_generic_to_shared(p);
    asm volatile("ldmatrix.sync.aligned.m8n8.x4.shared.b16 {%0,%1,%2,%3}, [%4];"
        : "=r"(r0), "=r"(r1), "=r"(r2), "=r"(r3) : "r"(a));
}
__device__ __forceinline__ void cpa16(void* sdst, const void* gsrc) {
    uint32_t s = (uint32_t)__cvta_generic_to_shared(sdst);
    asm volatile("cp.async.cg.shared.global [%0], [%1], 16;"
                 :: "r"(s), "l"(gsrc) : "memory");
}
#define CP_COMMIT() asm volatile("cp.async.commit_group;" ::: "memory")
#define CP_WAIT0()  asm volatile("cp.async.wait_group 0;" ::: "memory")

// ---------------- pair-mask bitmatrix ----------------------------------------
// bit k of g_mask[q][*]: (mac[q]!=mac[k]) & (job[q]!=job[k])
__global__ void __launch_bounds__(256) mask_kernel(const int* __restrict__ nodeT)
{
    __shared__ int smac[2048];
    __shared__ int sjob[2048];
    int tid = threadIdx.x;
    for (int i = tid; i < 2048; i += 256) {
        smac[i] = nodeT[i*3 + 2];
        sjob[i] = nodeT[i*3 + 0];
    }
    __syncthreads();
    int w = tid >> 5, lane = tid & 31;
    int qr = blockIdx.x * 8 + w;
    int mq = smac[qr], jq = sjob[qr];
    for (int wd = 0; wd < 64; wd++) {
        int kk = wd*32 + lane;
        int bit = (mq != smac[kk]) & (jq != sjob[kk]);
        uint32_t word = __ballot_sync(0xffffffffu, bit);
        if (lane == 0) g_mask[qr*64 + wd] = word;
    }
}

// ---------------- fused dual LayerNorm --------------------------------------
__global__ void __launch_bounds__(256) ln_kernel(
    const float* __restrict__ x, const float* __restrict__ emb,
    const float* __restrict__ g, const float* __restrict__ bta,
    float* __restrict__ qk_in, float* __restrict__ v_in)
{
    int row  = blockIdx.x * 8 + (threadIdx.x >> 5);
    int lane = threadIdx.x & 31;
    size_t base = (size_t)row * 32 + lane;

    float4 xv = ((const float4*)x)[base];
    float4 ev = ((const float4*)emb)[base];
    float4 g4 = ((const float4*)g)[lane];
    float4 b4 = ((const float4*)bta)[lane];

    float4 t = make_float4(xv.x+ev.x, xv.y+ev.y, xv.z+ev.z, xv.w+ev.w);
    float s = t.x + t.y + t.z + t.w;
    #pragma unroll
    for (int o = 16; o; o >>= 1) s += __shfl_xor_sync(0xffffffffu, s, o);
    float mu = s * (1.0f/128.0f);
    float dx = t.x-mu, dy = t.y-mu, dz = t.z-mu, dw = t.w-mu;
    float v2 = dx*dx + dy*dy + dz*dz + dw*dw;
    #pragma unroll
    for (int o = 16; o; o >>= 1) v2 += __shfl_xor_sync(0xffffffffu, v2, o);
    float r = rsqrtf(v2 * (1.0f/128.0f) + 1e-5f);
    ((float4*)qk_in)[base] = make_float4(dx*r*g4.x + b4.x, dy*r*g4.y + b4.y,
                                         dz*r*g4.z + b4.z, dw*r*g4.w + b4.w);

    s = xv.x + xv.y + xv.z + xv.w;
    #pragma unroll
    for (int o = 16; o; o >>= 1) s += __shfl_xor_sync(0xffffffffu, s, o);
    mu = s * (1.0f/128.0f);
    dx = xv.x-mu; dy = xv.y-mu; dz = xv.z-mu; dw = xv.w-mu;
    v2 = dx*dx + dy*dy + dz*dz + dw*dw;
    #pragma unroll
    for (int o = 16; o; o >>= 1) v2 += __shfl_xor_sync(0xffffffffu, v2, o);
    r = rsqrtf(v2 * (1.0f/128.0f) + 1e-5f);
    ((float4*)v_in)[base] = make_float4(dx*r*g4.x + b4.x, dy*r*g4.y + b4.y,
                                        dz*r*g4.z + b4.z, dw*r*g4.w + b4.w);
}

// ================= tf32 tensor-core GEMM: C = A(MxK) * W(NxK)^T + bias ======
// CTA tile 128x128, k-chunk 32, 8 warps = 4x2, warp tile 32x64.
// MODE 2: out[r,n] = addsrc[r,n] + val
// MODE 3: out[r,n] = 2*relu(val)
// MODE 4: fused QKV: grid.y 0,1 -> A=qk_in, scatter q/k (f16, q scaled);
//                    grid.y 2   -> A=addsrc(v_in), scatter v (f16, transposed)
template<int MODE>
__global__ void __launch_bounds__(256, 2) gemm_tc(
    const float* __restrict__ A, const float* __restrict__ W,
    const float* __restrict__ bias, const float* __restrict__ addsrc,
    float* __restrict__ out, int N, int K,
    __half* __restrict__ p0, __half* __restrict__ p1, __half* __restrict__ p2)
{
    __shared__ uint32_t As[128*40];
    __shared__ uint32_t Ws[128*40];

    int m0 = blockIdx.x * 128, n0 = blockIdx.y * 128;
    int tid = threadIdx.x;
    int w = tid >> 5, lane = tid & 31, g = lane >> 2, tg = lane & 3;
    int wm = w >> 1, wn = w & 1;

    const float* Asrc = (MODE == 4 && blockIdx.y == 2) ? addsrc : A;

    float c[2][8][4];
    #pragma unroll
    for (int mt = 0; mt < 2; mt++)
        #pragma unroll
        for (int j = 0; j < 8; j++)
            #pragma unroll
            for (int i = 0; i < 4; i++) c[mt][j][i] = 0.f;

    int fr = tid >> 1, hf = tid & 1;
    const float* Ar = Asrc + (size_t)(m0 + fr) * K + 16*hf;
    const float* Wr = W + (size_t)(n0 + fr) * K + 16*hf;
    int sbase = fr*40 + hf*16;

    for (int kc = 0; kc < K; kc += 32) {
        __syncthreads();
        float4 a0 = *(const float4*)(Ar + kc),     a1 = *(const float4*)(Ar + kc + 4);
        float4 a2 = *(const float4*)(Ar + kc + 8), a3 = *(const float4*)(Ar + kc + 12);
        float4 w0 = *(const float4*)(Wr + kc),     w1 = *(const float4*)(Wr + kc + 4);
        float4 w2 = *(const float4*)(Wr + kc + 8), w3 = *(const float4*)(Wr + kc + 12);
        *(uint2*)&As[sbase+0]  = make_uint2(cvt_tf32(a0.x), cvt_tf32(a1.x));
        *(uint2*)&As[sbase+2]  = make_uint2(cvt_tf32(a0.y), cvt_tf32(a1.y));
        *(uint2*)&As[sbase+4]  = make_uint2(cvt_tf32(a0.z), cvt_tf32(a1.z));
        *(uint2*)&As[sbase+6]  = make_uint2(cvt_tf32(a0.w), cvt_tf32(a1.w));
        *(uint2*)&As[sbase+8]  = make_uint2(cvt_tf32(a2.x), cvt_tf32(a3.x));
        *(uint2*)&As[sbase+10] = make_uint2(cvt_tf32(a2.y), cvt_tf32(a3.y));
        *(uint2*)&As[sbase+12] = make_uint2(cvt_tf32(a2.z), cvt_tf32(a3.z));
        *(uint2*)&As[sbase+14] = make_uint2(cvt_tf32(a2.w), cvt_tf32(a3.w));
        *(uint2*)&Ws[sbase+0]  = make_uint2(cvt_tf32(w0.x), cvt_tf32(w1.x));
        *(uint2*)&Ws[sbase+2]  = make_uint2(cvt_tf32(w0.y), cvt_tf32(w1.y));
        *(uint2*)&Ws[sbase+4]  = make_uint2(cvt_tf32(w0.z), cvt_tf32(w1.z));
        *(uint2*)&Ws[sbase+6]  = make_uint2(cvt_tf32(w0.w), cvt_tf32(w1.w));
        *(uint2*)&Ws[sbase+8]  = make_uint2(cvt_tf32(w2.x), cvt_tf32(w3.x));
        *(uint2*)&Ws[sbase+10] = make_uint2(cvt_tf32(w2.y), cvt_tf32(w3.y));
        *(uint2*)&Ws[sbase+12] = make_uint2(cvt_tf32(w2.z), cvt_tf32(w3.z));
        *(uint2*)&Ws[sbase+14] = make_uint2(cvt_tf32(w2.w), cvt_tf32(w3.w));
        __syncthreads();

        #pragma unroll
        for (int ks = 0; ks < 4; ks++) {
            uint2 bf[8];
            #pragma unroll
            for (int j = 0; j < 8; j++)
                bf[j] = *(const uint2*)&Ws[(64*wn + 8*j + g)*40 + ks*8 + 2*tg];
            #pragma unroll
            for (int mt = 0; mt < 2; mt++) {
                uint2 aa = *(const uint2*)&As[(32*wm + 16*mt + g)*40 + ks*8 + 2*tg];
                uint2 ab = *(const uint2*)&As[(32*wm + 16*mt + g + 8)*40 + ks*8 + 2*tg];
                #pragma unroll
                for (int j = 0; j < 8; j++)
                    mma_tf32(c[mt][j], aa.x, ab.x, aa.y, ab.y, bf[j].x, bf[j].y);
            }
        }
    }

    #pragma unroll
    for (int mt = 0; mt < 2; mt++) {
        int r0 = m0 + 32*wm + 16*mt + g;
        int r1 = r0 + 8;
        #pragma unroll
        for (int j = 0; j < 8; j++) {
            int n = n0 + 64*wn + 8*j + 2*tg;
            float2 bs = *(const float2*)(bias + n);
            float v00 = c[mt][j][0] + bs.x, v01 = c[mt][j][1] + bs.y;
            float v10 = c[mt][j][2] + bs.x, v11 = c[mt][j][3] + bs.y;
            if (MODE == 4) {
                int b0i = r0 >> 11, s0i = r0 & 2047;
                int b1i = r1 >> 11, s1i = r1 & 2047;
                if (n < 256) {
                    if (n < 128) { v00 *= QSCALE; v01 *= QSCALE; v10 *= QSCALE; v11 *= QSCALE; }
                    __half* dst = (n < 128) ? p0 : p1;
                    int e = n & 127, hh = e >> 6, dh = e & 63;
                    *(uint32_t*)&dst[((size_t)(b0i*2 + hh)*2048 + s0i)*64 + dh] = pack_f16(v01, v00);
                    *(uint32_t*)&dst[((size_t)(b1i*2 + hh)*2048 + s1i)*64 + dh] = pack_f16(v11, v10);
                } else {
                    int e = n - 256, hh = e >> 6, dh = e & 63;
                    p2[((size_t)(b0i*2 + hh)*64 + dh    )*2048 + s0i] = __float2half_rn(v00);
                    p2[((size_t)(b0i*2 + hh)*64 + dh + 1)*2048 + s0i] = __float2half_rn(v01);
                    p2[((size_t)(b1i*2 + hh)*64 + dh    )*2048 + s1i] = __float2half_rn(v10);
                    p2[((size_t)(b1i*2 + hh)*64 + dh + 1)*2048 + s1i] = __float2half_rn(v11);
                }
            } else if (MODE == 2) {
                float2 s0 = *(const float2*)(addsrc + (size_t)r0*N + n);
                float2 s1 = *(const float2*)(addsrc + (size_t)r1*N + n);
                *(float2*)(out + (size_t)r0*N + n) = make_float2(s0.x + v00, s0.y + v01);
                *(float2*)(out + (size_t)r1*N + n) = make_float2(s1.x + v10, s1.y + v11);
            } else {
                *(float2*)(out + (size_t)r0*N + n) =
                    make_float2(2.f*fmaxf(v00, 0.f), 2.f*fmaxf(v01, 0.f));
                *(float2*)(out + (size_t)r1*N + n) =
                    make_float2(2.f*fmaxf(v10, 0.f), 2.f*fmaxf(v11, 0.f));
            }
        }
    }
}

// ================= f16 ldmatrix flash attention ==============================
// grid (S/128, B*H), 256 threads (8 warps). Q tile 128, K tile 64, DH=64.
// cp.async double-buffered K/V; bitmask mask; ex2.f16x2 softmax; l via ones-mma.
#define ONES16 0x3C003C00u

__global__ void __launch_bounds__(256, 2) attn_f16_kernel(
    const __half* __restrict__ q, const __half* __restrict__ k,
    const __half* __restrict__ v, const int* __restrict__ actions,
    float* __restrict__ ctx)
{
    __shared__ uint4 Qs[1024];     // 128 rows x 128B (q rows x dh), swizzled
    __shared__ uint4 Ks[2][512];   // 64 rows (kcol) x 128B (dh)
    __shared__ uint4 Vs[2][512];   // 64 rows (dh) x 128B (kcol)

    int tid = threadIdx.x;
    int w = tid >> 5, lane = tid & 31;
    int g = lane >> 2, tg = lane & 3;
    int bh = blockIdx.y, b = bh >> 1, h = bh & 1;
    int q0 = blockIdx.x * 128;

    // ---- Q tile fill (swizzled STS.128) ----
    const uint4* qg = (const uint4*)(q + ((size_t)bh * S_ + q0) * 64);
    #pragma unroll
    for (int it = 0; it < 4; it++) {
        int i = tid + 256*it;
        int r = i >> 3, cc = i & 7;
        Qs[r*8 + (cc ^ (r & 7))] = qg[i];
    }

    int rq0 = q0 + 16*w + g, rq1 = rq0 + 8;
    int aq0 = (actions[b*S_ + rq0] == 0);
    int aq1 = (actions[b*S_ + rq1] == 0);
    const uint32_t* mr0 = g_mask + rq0*64;
    const uint32_t* mr1 = g_mask + rq1*64;
    uint32_t nw00 = mr0[0], nw01 = mr0[1];
    uint32_t nw10 = mr1[0], nw11 = mr1[1];

    const uint4* kg = (const uint4*)(k + (size_t)bh * S_ * 64);
    const uint4* vg = (const uint4*)(v + (size_t)bh * 64 * S_);

    // tile fill mapping: row fr (0..63), chunks 2*fq, 2*fq+1 (swizzled)
    int fr = tid >> 2, fq = tid & 3;
    int sx0 = fr*8 + ((2*fq)   ^ (fr & 7));
    int sx1 = fr*8 + ((2*fq+1) ^ (fr & 7));

    // prologue: tile 0 -> buffer 0
    cpa16(&Ks[0][sx0], kg + (size_t)fr*8 + 2*fq);
    cpa16(&Ks[0][sx1], kg + (size_t)fr*8 + 2*fq + 1);
    cpa16(&Vs[0][sx0], vg + (size_t)fr*256 + 2*fq);
    cpa16(&Vs[0][sx1], vg + (size_t)fr*256 + 2*fq + 1);
    CP_COMMIT();

    // fragment lane geometry
    int rowq = 16*w + (lane & 7) + 8*((lane >> 3) & 1);
    int cbq  = lane >> 4;
    int xq   = rowq & 7;
    const uint4* aqrow = Qs + rowq*8;
    int rowk = (lane & 7) + 8*(lane >> 4);
    int cbk  = (lane >> 3) & 1;
    int xk   = rowk & 7;

    float o[8][4];
    #pragma unroll
    for (int j = 0; j < 8; j++)
        #pragma unroll
        for (int i = 0; i < 4; i++) o[j][i] = 0.f;
    float o9[4] = {0.f, 0.f, 0.f, 0.f};     // row-sum accumulator (ones column)

    for (int kt = 0; kt < 32; kt++) {
        CP_WAIT0();
        __syncthreads();          // current tile visible to all; prev readers done
        int cur = kt & 1;
        if (kt < 31) {            // issue next tile into other buffer
            int kn = (kt + 1) * 64, nb = cur ^ 1;
            cpa16(&Ks[nb][sx0], kg + (size_t)(kn + fr)*8 + 2*fq);
            cpa16(&Ks[nb][sx1], kg + (size_t)(kn + fr)*8 + 2*fq + 1);
            cpa16(&Vs[nb][sx0], vg + (size_t)fr*256 + (kn >> 3) + 2*fq);
            cpa16(&Vs[nb][sx1], vg + (size_t)fr*256 + (kn >> 3) + 2*fq + 1);
            CP_COMMIT();
        }
        const uint4* akrow = Ks[cur] + rowk*8;
        const uint4* avrow = Vs[cur] + rowk*8;

        // ---- S = Q K^T ----
        float c[8][4];
        #pragma unroll
        for (int j = 0; j < 8; j++)
            #pragma unroll
            for (int i = 0; i < 4; i++) c[j][i] = 0.f;
        #pragma unroll
        for (int ks = 0; ks < 4; ks++) {
            uint32_t qa0, qa1, qa2, qa3;
            ldsm4(qa0, qa1, qa2, qa3, aqrow + ((2*ks + cbq) ^ xq));
            int ck = (2*ks + cbk) ^ xk;
            #pragma unroll
            for (int J = 0; J < 4; J++) {
                uint32_t b0, b1, b2, b3;
                ldsm4(b0, b1, b2, b3, akrow + J*128 + ck);
                mma_f16(c[2*J],   qa0, qa1, qa2, qa3, b0, b1);
                mma_f16(c[2*J+1], qa0, qa1, qa2, qa3, b2, b3);
            }
        }

        // ---- mask words for this tile (actions folded; pre-shifted by 2*tg) ----
        uint32_t wsh00 = aq0 ? (nw00 >> (2*tg)) : 0u;
        uint32_t wsh01 = aq0 ? (nw01 >> (2*tg)) : 0u;
        uint32_t wsh10 = aq1 ? (nw10 >> (2*tg)) : 0u;
        uint32_t wsh11 = aq1 ? (nw11 >> (2*tg)) : 0u;
        if (kt < 31) {
            nw00 = mr0[kt*2 + 2]; nw01 = mr0[kt*2 + 3];
            nw10 = mr1[kt*2 + 2]; nw11 = mr1[kt*2 + 3];
        }

        // ---- masked exp: p packed f16x2, directly the PV A-fragments ----
        uint32_t pj0[8], pj1[8];
        #pragma unroll
        for (int j = 0; j < 8; j++) {
            uint32_t w0 = (j < 4) ? wsh00 : wsh01;
            uint32_t w1 = (j < 4) ? wsh10 : wsh11;
            int sh = 8*(j & 3);
            uint32_t bt0 = w0 >> sh, bt1 = w1 >> sh;
            float s00 = (bt0 & 1u) ? -100.f : c[j][0];
            float s01 = (bt0 & 2u) ? -100.f : c[j][1];
            float s10 = (bt1 & 1u) ? -100.f : c[j][2];
            float s11 = (bt1 & 2u) ? -100.f : c[j][3];
            pj0[j] = ex2h2(pack_f16(s01, s00));
            pj1[j] = ex2h2(pack_f16(s11, s10));
        }

        // ---- O += P V ; row-sum l += P * ones (tensor core) ----
        #pragma unroll
        for (int ks = 0; ks < 4; ks++) {
            uint32_t a0 = pj0[2*ks],   a1 = pj1[2*ks];
            uint32_t a2 = pj0[2*ks+1], a3 = pj1[2*ks+1];
            mma_f16(o9, a0, a1, a2, a3, ONES16, ONES16);
            int cv = (2*ks + cbk) ^ xk;
            #pragma unroll
            for (int J = 0; J < 4; J++) {
                uint32_t b0, b1, b2, b3;
                ldsm4(b0, b1, b2, b3, avrow + J*128 + cv);
                mma_f16(o[2*J],   a0, a1, a2, a3, b0, b1);
                mma_f16(o[2*J+1], a0, a1, a2, a3, b2, b3);
            }
        }
    }

    float inv0 = 1.0f / o9[0];   // all ones-columns equal: o9[0] = l(row rq0)
    float inv1 = 1.0f / o9[2];   // o9[2] = l(row rq1)

    float* og0 = ctx + ((size_t)b*S_ + rq0)*128 + h*64;
    float* og1 = ctx + ((size_t)b*S_ + rq1)*128 + h*64;
    #pragma unroll
    for (int j = 0; j < 8; j++) {
        int c0 = 8*j + 2*tg;
        *(float2*)(og0 + c0) = make_float2(o[j][0]*inv0, o[j][1]*inv0);
        *(float2*)(og1 + c0) = make_float2(o[j][2]*inv1, o[j][3]*inv1);
    }
}

// ---------------- launcher ---------------------------------------------------
extern "C" void kernel_launch(void* const* d_in, const int* in_sizes, int n_in,
                              void* d_out, int out_size)
{
    const float* x    = (const float*)d_in[0];
    const float* emb  = (const float*)d_in[1];
    const int*   act  = (const int*)  d_in[2];
    const int*   node = (const int*)  d_in[3];
    const float* Wqkv = (const float*)d_in[4];
    const float* bqkv = (const float*)d_in[5];
    const float* Wo   = (const float*)d_in[6];
    const float* bo   = (const float*)d_in[7];
    const float* lng  = (const float*)d_in[8];
    const float* lnb  = (const float*)d_in[9];
    const float* W1   = (const float*)d_in[10];
    const float* b1   = (const float*)d_in[11];
    const float* W2   = (const float*)d_in[12];
    const float* b2   = (const float*)d_in[13];
    float* out = (float*)d_out;

    float *qk_in, *v_in, *ctx, *x2, *hb;
    __half *qp, *kp, *vp;
    cudaGetSymbolAddress((void**)&qk_in, g_qk_in);
    cudaGetSymbolAddress((void**)&v_in,  g_v_in);
    cudaGetSymbolAddress((void**)&qp,    g_q);
    cudaGetSymbolAddress((void**)&kp,    g_k);
    cudaGetSymbolAddress((void**)&vp,    g_v);
    cudaGetSymbolAddress((void**)&ctx,   g_ctx);
    cudaGetSymbolAddress((void**)&x2,    g_x2);
    cudaGetSymbolAddress((void**)&hb,    g_hb);

    mask_kernel<<<256, 256>>>(node);
    ln_kernel<<<ROWS/8, 256>>>(x, emb, lng, lnb, qk_in, v_in);

    // fused QKV projection: y<2 -> q/k from qk_in, y==2 -> v from v_in
    gemm_tc<4><<<dim3(ROWS/128, 3), 256>>>(qk_in, Wqkv, bqkv, v_in, nullptr,
                                           384, 128, qp, kp, vp);

    attn_f16_kernel<<<dim3(S_/128, 16), 256>>>(qp, kp, vp, act, ctx);

    gemm_tc<2><<<dim3(ROWS/128, 1), 256>>>(ctx, Wo, bo, x, x2,
                                           128, 128, nullptr, nullptr, nullptr);
    gemm_tc<3><<<dim3(ROWS/128, 2), 256>>>(x2, W1, b1, nullptr, hb,
                                           256, 128, nullptr, nullptr, nullptr);
    gemm_tc<2><<<dim3(ROWS/128, 1), 256>>>(hb, W2, b2, x2, out,
                                           128, 256, nullptr, nullptr, nullptr);
}

// round 7
// speedup vs baseline: 6.7188x; 1.3369x over previous
#include <cuda_runtime.h>
#include <cuda_fp16.h>
#include <cstdint>

#define B_   8
#define S_   2048
#define D_   128
#define ROWS (B_*S_)            // 16384
#define QSCALE 0.18033688011112042f   // log2(e)/8

// ---------------- scratch (static device memory; no allocation) -------------
__device__ __half g_qk_h[ROWS*D_];          // LN(x+emb) f16
__device__ __half g_v_h [ROWS*D_];          // LN(x) f16
__device__ __half g_q[16*S_*64];            // (b,h,s,dh), pre-scaled by log2e/8
__device__ __half g_k[16*S_*64];            // (b,h,s,dh)
__device__ __half g_v[16*64*S_];            // (b,h,dh,s)
__device__ __half g_ctx_h[ROWS*D_];         // attention out, f16
__device__ float  g_x2 [ROWS*D_];           // residual trunk, fp32
__device__ __half g_x2_h[ROWS*D_];          // f16 copy for FFN1
__device__ __half g_hb_h[ROWS*2*D_];        // FFN hidden, f16
__device__ uint32_t g_mask[S_*64];          // pair mask bits: [q][k>>5] bit (k&31)
__device__ __half g_wh[131072];             // f16 weights: qkv | out | l1 | l2

#define WOFF_QKV 0
#define WOFF_O   49152
#define WOFF_1   65536
#define WOFF_2   98304

// ---------------- helpers ----------------------------------------------------
__device__ __forceinline__ uint32_t pack_f16(float hi, float lo) {
    uint32_t d;
    asm("cvt.rn.f16x2.f32 %0, %1, %2;" : "=r"(d) : "f"(hi), "f"(lo));
    return d;
}
__device__ __forceinline__ uint32_t ex2h2(uint32_t x) {
    asm("ex2.approx.f16x2 %0, %0;" : "+r"(x));
    return x;
}
__device__ __forceinline__ void mma_f16(float* d, uint32_t a0, uint32_t a1,
                                        uint32_t a2, uint32_t a3,
                                        uint32_t b0, uint32_t b1) {
    asm volatile("mma.sync.aligned.m16n8k16.row.col.f32.f16.f16.f32 "
        "{%0,%1,%2,%3}, {%4,%5,%6,%7}, {%8,%9}, {%0,%1,%2,%3};"
        : "+f"(d[0]), "+f"(d[1]), "+f"(d[2]), "+f"(d[3])
        : "r"(a0), "r"(a1), "r"(a2), "r"(a3), "r"(b0), "r"(b1));
}
__device__ __forceinline__ void ldsm4(uint32_t& r0, uint32_t& r1,
                                      uint32_t& r2, uint32_t& r3,
                                      const void* p) {
    uint32_t a = (uint32_t)__cvta_generic_to_shared(p);
    asm volatile("ldmatrix.sync.aligned.m8n8.x4.shared.b16 {%0,%1,%2,%3}, [%4];"
        : "=r"(r0), "=r"(r1), "=r"(r2), "=r"(r3) : "r"(a));
}
__device__ __forceinline__ void cpa16(void* sdst, const void* gsrc) {
    uint32_t s = (uint32_t)__cvta_generic_to_shared(sdst);
    asm volatile("cp.async.cg.shared.global [%0], [%1], 16;"
                 :: "r"(s), "l"(gsrc) : "memory");
}
#define CP_COMMIT() asm volatile("cp.async.commit_group;" ::: "memory")
#define CP_WAIT0()  asm volatile("cp.async.wait_group 0;" ::: "memory")

// ---------------- weight f16 conversion --------------------------------------
__global__ void __launch_bounds__(256) prep_w(
    const float* __restrict__ wqkv, const float* __restrict__ wo,
    const float* __restrict__ w1,   const float* __restrict__ w2)
{
    for (int i = blockIdx.x*256 + threadIdx.x; i < 131072; i += gridDim.x*256) {
        float v;
        if (i < 49152)       v = wqkv[i];
        else if (i < 65536)  v = wo[i - 49152];
        else if (i < 98304)  v = w1[i - 65536];
        else                 v = w2[i - 98304];
        g_wh[i] = __float2half_rn(v);
    }
}

// ---------------- pair-mask bitmatrix ----------------------------------------
__global__ void __launch_bounds__(256) mask_kernel(const int* __restrict__ nodeT)
{
    __shared__ int smac[2048];
    __shared__ int sjob[2048];
    int tid = threadIdx.x;
    for (int i = tid; i < 2048; i += 256) {
        smac[i] = nodeT[i*3 + 2];
        sjob[i] = nodeT[i*3 + 0];
    }
    __syncthreads();
    int w = tid >> 5, lane = tid & 31;
    int qr = blockIdx.x * 8 + w;
    int mq = smac[qr], jq = sjob[qr];
    for (int wd = 0; wd < 64; wd++) {
        int kk = wd*32 + lane;
        int bit = (mq != smac[kk]) & (jq != sjob[kk]);
        uint32_t word = __ballot_sync(0xffffffffu, bit);
        if (lane == 0) g_mask[qr*64 + wd] = word;
    }
}

// ---------------- fused dual LayerNorm (f16 out) -----------------------------
__global__ void __launch_bounds__(256) ln_kernel(
    const float* __restrict__ x, const float* __restrict__ emb,
    const float* __restrict__ g, const float* __restrict__ bta)
{
    int row  = blockIdx.x * 8 + (threadIdx.x >> 5);
    int lane = threadIdx.x & 31;
    size_t base = (size_t)row * 32 + lane;

    float4 xv = ((const float4*)x)[base];
    float4 ev = ((const float4*)emb)[base];
    float4 g4 = ((const float4*)g)[lane];
    float4 b4 = ((const float4*)bta)[lane];

    float4 t = make_float4(xv.x+ev.x, xv.y+ev.y, xv.z+ev.z, xv.w+ev.w);
    float s = t.x + t.y + t.z + t.w;
    #pragma unroll
    for (int o = 16; o; o >>= 1) s += __shfl_xor_sync(0xffffffffu, s, o);
    float mu = s * (1.0f/128.0f);
    float dx = t.x-mu, dy = t.y-mu, dz = t.z-mu, dw = t.w-mu;
    float v2 = dx*dx + dy*dy + dz*dz + dw*dw;
    #pragma unroll
    for (int o = 16; o; o >>= 1) v2 += __shfl_xor_sync(0xffffffffu, v2, o);
    float r = rsqrtf(v2 * (1.0f/128.0f) + 1e-5f);
    ((uint2*)g_qk_h)[base] = make_uint2(
        pack_f16(dy*r*g4.y + b4.y, dx*r*g4.x + b4.x),
        pack_f16(dw*r*g4.w + b4.w, dz*r*g4.z + b4.z));

    s = xv.x + xv.y + xv.z + xv.w;
    #pragma unroll
    for (int o = 16; o; o >>= 1) s += __shfl_xor_sync(0xffffffffu, s, o);
    mu = s * (1.0f/128.0f);
    dx = xv.x-mu; dy = xv.y-mu; dz = xv.z-mu; dw = xv.w-mu;
    v2 = dx*dx + dy*dy + dz*dz + dw*dw;
    #pragma unroll
    for (int o = 16; o; o >>= 1) v2 += __shfl_xor_sync(0xffffffffu, v2, o);
    r = rsqrtf(v2 * (1.0f/128.0f) + 1e-5f);
    ((uint2*)g_v_h)[base] = make_uint2(
        pack_f16(dy*r*g4.y + b4.y, dx*r*g4.x + b4.x),
        pack_f16(dw*r*g4.w + b4.w, dz*r*g4.z + b4.z));
}

// ================= f16 tensor-core GEMM: C = A(MxK) * W(NxK)^T + bias =======
// CTA tile 128x128, k-chunk 64 (double-buffered cp.async), 8 warps = 4x2,
// warp tile 32x64. Swizzled tiles + ldmatrix.
// MODE 2: out[r,n] = addsrc[r,n] + val (f32); if outh, also f16 copy
// MODE 3: outh[r,n] = f16(2*relu(val))
// MODE 4: fused QKV: grid.y<2 -> A, scatter q/k; grid.y==2 -> A2, scatter v
template<int MODE>
__global__ void __launch_bounds__(256, 2) gemm_f16k(
    const __half* __restrict__ A, const __half* __restrict__ A2,
    const __half* __restrict__ W, const float* __restrict__ bias,
    const float* __restrict__ addsrc, float* __restrict__ out,
    __half* __restrict__ outh, int N, int K,
    __half* __restrict__ p0, __half* __restrict__ p1, __half* __restrict__ p2)
{
    extern __shared__ uint4 dsm[];
    uint4* As = dsm;          // [2][1024]: 128 rows x 8 chunks(16B), swizzled
    uint4* Ws = dsm + 2048;   // [2][1024]

    int m0 = blockIdx.x * 128, n0 = blockIdx.y * 128;
    int tid = threadIdx.x;
    int w = tid >> 5, lane = tid & 31, g = lane >> 2, tg = lane & 3;
    int wm = w >> 1, wn = w & 1;

    const __half* Asrc = (MODE == 4 && blockIdx.y == 2) ? A2 : A;

    float c[2][8][4];
    #pragma unroll
    for (int mt = 0; mt < 2; mt++)
        #pragma unroll
        for (int j = 0; j < 8; j++)
            #pragma unroll
            for (int i = 0; i < 4; i++) c[mt][j][i] = 0.f;

    // fill: thread covers 4 (row, chunk) slots per matrix per chunk-iter
    // prologue chunk 0 -> buffer 0
    #pragma unroll
    for (int it = 0; it < 4; it++) {
        int i = tid + 256*it;
        int r = i >> 3, cc = i & 7;
        int sd = r*8 + (cc ^ (r & 7));
        cpa16(&As[sd], Asrc + (size_t)(m0 + r)*K + cc*8);
        cpa16(&Ws[sd], W    + (size_t)(n0 + r)*K + cc*8);
    }
    CP_COMMIT();

    int nch = K >> 6;
    int la15 = lane & 15, xq = lane & 7, cbq = lane >> 4;
    int rowk = (lane & 7) + 8*(lane >> 4);
    int cbk  = (lane >> 3) & 1;
    int xk   = rowk & 7;

    for (int ic = 0; ic < nch; ic++) {
        CP_WAIT0();
        __syncthreads();
        int cur = ic & 1;
        if (ic + 1 < nch) {
            int nb = cur ^ 1, kc = (ic + 1) * 64;
            #pragma unroll
            for (int it = 0; it < 4; it++) {
                int i = tid + 256*it;
                int r = i >> 3, cc = i & 7;
                int sd = nb*1024 + r*8 + (cc ^ (r & 7));
                cpa16(&As[sd], Asrc + (size_t)(m0 + r)*K + kc + cc*8);
                cpa16(&Ws[sd], W    + (size_t)(n0 + r)*K + kc + cc*8);
            }
            CP_COMMIT();
        }
        const uint4* Ac = As + cur*1024;
        const uint4* Wc = Ws + cur*1024;

        #pragma unroll
        for (int ks = 0; ks < 4; ks++) {
            uint32_t a[2][4];
            #pragma unroll
            for (int mt = 0; mt < 2; mt++)
                ldsm4(a[mt][0], a[mt][1], a[mt][2], a[mt][3],
                      Ac + (32*wm + 16*mt + la15)*8 + ((2*ks + cbq) ^ xq));
            int ck = (2*ks + cbk) ^ xk;
            #pragma unroll
            for (int J = 0; J < 4; J++) {
                uint32_t b0, b1, b2, b3;
                ldsm4(b0, b1, b2, b3, Wc + (64*wn + J*16 + rowk)*8 + ck);
                #pragma unroll
                for (int mt = 0; mt < 2; mt++) {
                    mma_f16(c[mt][2*J],   a[mt][0], a[mt][1], a[mt][2], a[mt][3], b0, b1);
                    mma_f16(c[mt][2*J+1], a[mt][0], a[mt][1], a[mt][2], a[mt][3], b2, b3);
                }
            }
        }
    }

    // ---- epilogue ----
    #pragma unroll
    for (int mt = 0; mt < 2; mt++) {
        int r0 = m0 + 32*wm + 16*mt + g;
        int r1 = r0 + 8;
        #pragma unroll
        for (int j = 0; j < 8; j++) {
            int n = n0 + 64*wn + 8*j + 2*tg;
            float2 bs = *(const float2*)(bias + n);
            float v00 = c[mt][j][0] + bs.x, v01 = c[mt][j][1] + bs.y;
            float v10 = c[mt][j][2] + bs.x, v11 = c[mt][j][3] + bs.y;
            if (MODE == 4) {
                int b0i = r0 >> 11, s0i = r0 & 2047;
                int b1i = r1 >> 11, s1i = r1 & 2047;
                if (n < 256) {
                    if (n < 128) { v00 *= QSCALE; v01 *= QSCALE; v10 *= QSCALE; v11 *= QSCALE; }
                    __half* dst = (n < 128) ? p0 : p1;
                    int e = n & 127, hh = e >> 6, dh = e & 63;
                    *(uint32_t*)&dst[((size_t)(b0i*2 + hh)*2048 + s0i)*64 + dh] = pack_f16(v01, v00);
                    *(uint32_t*)&dst[((size_t)(b1i*2 + hh)*2048 + s1i)*64 + dh] = pack_f16(v11, v10);
                } else {
                    int e = n - 256, hh = e >> 6, dh = e & 63;
                    p2[((size_t)(b0i*2 + hh)*64 + dh    )*2048 + s0i] = __float2half_rn(v00);
                    p2[((size_t)(b0i*2 + hh)*64 + dh + 1)*2048 + s0i] = __float2half_rn(v01);
                    p2[((size_t)(b1i*2 + hh)*64 + dh    )*2048 + s1i] = __float2half_rn(v10);
                    p2[((size_t)(b1i*2 + hh)*64 + dh + 1)*2048 + s1i] = __float2half_rn(v11);
                }
            } else if (MODE == 2) {
                float2 s0 = *(const float2*)(addsrc + (size_t)r0*N + n);
                float2 s1 = *(const float2*)(addsrc + (size_t)r1*N + n);
                float f00 = s0.x + v00, f01 = s0.y + v01;
                float f10 = s1.x + v10, f11 = s1.y + v11;
                *(float2*)(out + (size_t)r0*N + n) = make_float2(f00, f01);
                *(float2*)(out + (size_t)r1*N + n) = make_float2(f10, f11);
                if (outh) {
                    *(uint32_t*)&outh[(size_t)r0*N + n] = pack_f16(f01, f00);
                    *(uint32_t*)&outh[(size_t)r1*N + n] = pack_f16(f11, f10);
                }
            } else {   // MODE 3
                float f00 = 2.f*fmaxf(v00, 0.f), f01 = 2.f*fmaxf(v01, 0.f);
                float f10 = 2.f*fmaxf(v10, 0.f), f11 = 2.f*fmaxf(v11, 0.f);
                *(uint32_t*)&outh[(size_t)r0*N + n] = pack_f16(f01, f00);
                *(uint32_t*)&outh[(size_t)r1*N + n] = pack_f16(f11, f10);
            }
        }
    }
}

// ================= f16 ldmatrix flash attention ==============================
#define ONES16 0x3C003C00u

__global__ void __launch_bounds__(256, 2) attn_f16_kernel(
    const __half* __restrict__ q, const __half* __restrict__ k,
    const __half* __restrict__ v, const int* __restrict__ actions,
    __half* __restrict__ ctxh)
{
    __shared__ uint4 Qs[1024];     // 128 rows x 128B (q rows x dh), swizzled
    __shared__ uint4 Ks[2][512];   // 64 rows (kcol) x 128B (dh)
    __shared__ uint4 Vs[2][512];   // 64 rows (dh) x 128B (kcol)

    int tid = threadIdx.x;
    int w = tid >> 5, lane = tid & 31;
    int g = lane >> 2, tg = lane & 3;
    int bh = blockIdx.y, b = bh >> 1, h = bh & 1;
    int q0 = blockIdx.x * 128;

    const uint4* qg = (const uint4*)(q + ((size_t)bh * S_ + q0) * 64);
    #pragma unroll
    for (int it = 0; it < 4; it++) {
        int i = tid + 256*it;
        int r = i >> 3, cc = i & 7;
        Qs[r*8 + (cc ^ (r & 7))] = qg[i];
    }

    int rq0 = q0 + 16*w + g, rq1 = rq0 + 8;
    int aq0 = (actions[b*S_ + rq0] == 0);
    int aq1 = (actions[b*S_ + rq1] == 0);
    const uint32_t* mr0 = g_mask + rq0*64;
    const uint32_t* mr1 = g_mask + rq1*64;
    uint32_t nw00 = mr0[0], nw01 = mr0[1];
    uint32_t nw10 = mr1[0], nw11 = mr1[1];

    const uint4* kg = (const uint4*)(k + (size_t)bh * S_ * 64);
    const uint4* vg = (const uint4*)(v + (size_t)bh * 64 * S_);

    int fr = tid >> 2, fq = tid & 3;
    int sx0 = fr*8 + ((2*fq)   ^ (fr & 7));
    int sx1 = fr*8 + ((2*fq+1) ^ (fr & 7));

    cpa16(&Ks[0][sx0], kg + (size_t)fr*8 + 2*fq);
    cpa16(&Ks[0][sx1], kg + (size_t)fr*8 + 2*fq + 1);
    cpa16(&Vs[0][sx0], vg + (size_t)fr*256 + 2*fq);
    cpa16(&Vs[0][sx1], vg + (size_t)fr*256 + 2*fq + 1);
    CP_COMMIT();

    int rowq = 16*w + (lane & 7) + 8*((lane >> 3) & 1);
    int cbq  = lane >> 4;
    int xq   = rowq & 7;
    const uint4* aqrow = Qs + rowq*8;
    int rowk = (lane & 7) + 8*(lane >> 4);
    int cbk  = (lane >> 3) & 1;
    int xk   = rowk & 7;

    float o[8][4];
    #pragma unroll
    for (int j = 0; j < 8; j++)
        #pragma unroll
        for (int i = 0; i < 4; i++) o[j][i] = 0.f;
    float o9[4] = {0.f, 0.f, 0.f, 0.f};

    for (int kt = 0; kt < 32; kt++) {
        CP_WAIT0();
        __syncthreads();
        int cur = kt & 1;
        if (kt < 31) {
            int kn = (kt + 1) * 64, nb = cur ^ 1;
            cpa16(&Ks[nb][sx0], kg + (size_t)(kn + fr)*8 + 2*fq);
            cpa16(&Ks[nb][sx1], kg + (size_t)(kn + fr)*8 + 2*fq + 1);
            cpa16(&Vs[nb][sx0], vg + (size_t)fr*256 + (kn >> 3) + 2*fq);
            cpa16(&Vs[nb][sx1], vg + (size_t)fr*256 + (kn >> 3) + 2*fq + 1);
            CP_COMMIT();
        }
        const uint4* akrow = Ks[cur] + rowk*8;
        const uint4* avrow = Vs[cur] + rowk*8;

        float c[8][4];
        #pragma unroll
        for (int j = 0; j < 8; j++)
            #pragma unroll
            for (int i = 0; i < 4; i++) c[j][i] = 0.f;
        #pragma unroll
        for (int ks = 0; ks < 4; ks++) {
            uint32_t qa0, qa1, qa2, qa3;
            ldsm4(qa0, qa1, qa2, qa3, aqrow + ((2*ks + cbq) ^ xq));
            int ck = (2*ks + cbk) ^ xk;
            #pragma unroll
            for (int J = 0; J < 4; J++) {
                uint32_t b0, b1, b2, b3;
                ldsm4(b0, b1, b2, b3, akrow + J*128 + ck);
                mma_f16(c[2*J],   qa0, qa1, qa2, qa3, b0, b1);
                mma_f16(c[2*J+1], qa0, qa1, qa2, qa3, b2, b3);
            }
        }

        uint32_t wsh00 = aq0 ? (nw00 >> (2*tg)) : 0u;
        uint32_t wsh01 = aq0 ? (nw01 >> (2*tg)) : 0u;
        uint32_t wsh10 = aq1 ? (nw10 >> (2*tg)) : 0u;
        uint32_t wsh11 = aq1 ? (nw11 >> (2*tg)) : 0u;
        if (kt < 31) {
            nw00 = mr0[kt*2 + 2]; nw01 = mr0[kt*2 + 3];
            nw10 = mr1[kt*2 + 2]; nw11 = mr1[kt*2 + 3];
        }

        uint32_t pj0[8], pj1[8];
        #pragma unroll
        for (int j = 0; j < 8; j++) {
            uint32_t w0 = (j < 4) ? wsh00 : wsh01;
            uint32_t w1 = (j < 4) ? wsh10 : wsh11;
            int sh = 8*(j & 3);
            uint32_t bt0 = w0 >> sh, bt1 = w1 >> sh;
            float s00 = (bt0 & 1u) ? -100.f : c[j][0];
            float s01 = (bt0 & 2u) ? -100.f : c[j][1];
            float s10 = (bt1 & 1u) ? -100.f : c[j][2];
            float s11 = (bt1 & 2u) ? -100.f : c[j][3];
            pj0[j] = ex2h2(pack_f16(s01, s00));
            pj1[j] = ex2h2(pack_f16(s11, s10));
        }

        #pragma unroll
        for (int ks = 0; ks < 4; ks++) {
            uint32_t a0 = pj0[2*ks],   a1 = pj1[2*ks];
            uint32_t a2 = pj0[2*ks+1], a3 = pj1[2*ks+1];
            mma_f16(o9, a0, a1, a2, a3, ONES16, ONES16);
            int cv = (2*ks + cbk) ^ xk;
            #pragma unroll
            for (int J = 0; J < 4; J++) {
                uint32_t b0, b1, b2, b3;
                ldsm4(b0, b1, b2, b3, avrow + J*128 + cv);
                mma_f16(o[2*J],   a0, a1, a2, a3, b0, b1);
                mma_f16(o[2*J+1], a0, a1, a2, a3, b2, b3);
            }
        }
    }

    float inv0 = 1.0f / o9[0];
    float inv1 = 1.0f / o9[2];

    __half* og0 = ctxh + ((size_t)b*S_ + rq0)*128 + h*64;
    __half* og1 = ctxh + ((size_t)b*S_ + rq1)*128 + h*64;
    #pragma unroll
    for (int j = 0; j < 8; j++) {
        int c0 = 8*j + 2*tg;
        *(uint32_t*)(og0 + c0) = pack_f16(o[j][1]*inv0, o[j][0]*inv0);
        *(uint32_t*)(og1 + c0) = pack_f16(o[j][3]*inv1, o[j][2]*inv1);
    }
}

// ---------------- launcher ---------------------------------------------------
extern "C" void kernel_launch(void* const* d_in, const int* in_sizes, int n_in,
                              void* d_out, int out_size)
{
    const float* x    = (const float*)d_in[0];
    const float* emb  = (const float*)d_in[1];
    const int*   act  = (const int*)  d_in[2];
    const int*   node = (const int*)  d_in[3];
    const float* Wqkv = (const float*)d_in[4];
    const float* bqkv = (const float*)d_in[5];
    const float* Wo   = (const float*)d_in[6];
    const float* bo   = (const float*)d_in[7];
    const float* lng  = (const float*)d_in[8];
    const float* lnb  = (const float*)d_in[9];
    const float* W1   = (const float*)d_in[10];
    const float* b1   = (const float*)d_in[11];
    const float* W2   = (const float*)d_in[12];
    const float* b2   = (const float*)d_in[13];
    float* out = (float*)d_out;

    __half *qkh, *vh, *qp, *kp, *vp, *ctxh, *x2h, *hbh, *wh;
    float *x2;
    cudaGetSymbolAddress((void**)&qkh,  g_qk_h);
    cudaGetSymbolAddress((void**)&vh,   g_v_h);
    cudaGetSymbolAddress((void**)&qp,   g_q);
    cudaGetSymbolAddress((void**)&kp,   g_k);
    cudaGetSymbolAddress((void**)&vp,   g_v);
    cudaGetSymbolAddress((void**)&ctxh, g_ctx_h);
    cudaGetSymbolAddress((void**)&x2,   g_x2);
    cudaGetSymbolAddress((void**)&x2h,  g_x2_h);
    cudaGetSymbolAddress((void**)&hbh,  g_hb_h);
    cudaGetSymbolAddress((void**)&wh,   g_wh);

    cudaFuncSetAttribute(gemm_f16k<2>, cudaFuncAttributeMaxDynamicSharedMemorySize, 65536);
    cudaFuncSetAttribute(gemm_f16k<3>, cudaFuncAttributeMaxDynamicSharedMemorySize, 65536);
    cudaFuncSetAttribute(gemm_f16k<4>, cudaFuncAttributeMaxDynamicSharedMemorySize, 65536);

    prep_w<<<128, 256>>>(Wqkv, Wo, W1, W2);
    mask_kernel<<<256, 256>>>(node);
    ln_kernel<<<ROWS/8, 256>>>(x, emb, lng, lnb);

    // fused QKV projection (f16): y<2 -> q/k from qk_h, y==2 -> v from v_h
    gemm_f16k<4><<<dim3(ROWS/128, 3), 256, 65536>>>(
        qkh, vh, wh + WOFF_QKV, bqkv, nullptr, nullptr, nullptr,
        384, 128, qp, kp, vp);

    attn_f16_kernel<<<dim3(S_/128, 16), 256>>>(qp, kp, vp, act, ctxh);

    // out projection + residual: x2 = x + ctx @ Wo^T + bo  (f32 + f16 copy)
    gemm_f16k<2><<<dim3(ROWS/128, 1), 256, 65536>>>(
        ctxh, nullptr, wh + WOFF_O, bo, x, x2, x2h,
        128, 128, nullptr, nullptr, nullptr);
    // FFN1: hb = 2*relu(x2 @ W1^T + b1)  (f16)
    gemm_f16k<3><<<dim3(ROWS/128, 2), 256, 65536>>>(
        x2h, nullptr, wh + WOFF_1, b1, nullptr, nullptr, hbh,
        256, 128, nullptr, nullptr, nullptr);
    // FFN2 + residual: out = x2 + hb @ W2^T + b2  (f32)
    gemm_f16k<2><<<dim3(ROWS/128, 1), 256, 65536>>>(
        hbh, nullptr, wh + WOFF_2, b2, x2, out, nullptr,
        128, 256, nullptr, nullptr, nullptr);
}

// round 8
// speedup vs baseline: 6.9075x; 1.0281x over previous
#include <cuda_runtime.h>
#include <cuda_fp16.h>
#include <cstdint>

#define B_   8
#define S_   2048
#define D_   128
#define ROWS (B_*S_)            // 16384
#define QSCALE 0.18033688011112042f   // log2(e)/8

// ---------------- scratch (static device memory; no allocation) -------------
__device__ __half g_qk_h[ROWS*D_];          // LN(x+emb) f16
__device__ __half g_v_h [ROWS*D_];          // LN(x) f16
__device__ __half g_q[16*S_*64];            // (b,h,s,dh), pre-scaled by log2e/8
__device__ __half g_k[16*S_*64];            // (b,h,s,dh)
__device__ __half g_v[16*S_*64];            // (b,h,s,dh)  (trans-loaded in attn)
__device__ __half g_ctx_h[ROWS*D_];         // attention out, f16
__device__ float  g_x2 [ROWS*D_];           // residual trunk, fp32
__device__ __half g_x2_h[ROWS*D_];          // f16 copy for FFN1
__device__ __half g_hb_h[ROWS*2*D_];        // FFN hidden, f16
__device__ uint32_t g_mask[S_*64];          // pair mask bits: [q][k>>5] bit (k&31)
__device__ __half g_wh[131072];             // f16 weights: qkv | out | l1 | l2

#define WOFF_QKV 0
#define WOFF_O   49152
#define WOFF_1   65536
#define WOFF_2   98304

// ---------------- helpers ----------------------------------------------------
__device__ __forceinline__ uint32_t pack_f16(float hi, float lo) {
    uint32_t d;
    asm("cvt.rn.f16x2.f32 %0, %1, %2;" : "=r"(d) : "f"(hi), "f"(lo));
    return d;
}
__device__ __forceinline__ uint32_t ex2h2(uint32_t x) {
    asm("ex2.approx.f16x2 %0, %0;" : "+r"(x));
    return x;
}
__device__ __forceinline__ void mma_f16(float* d, uint32_t a0, uint32_t a1,
                                        uint32_t a2, uint32_t a3,
                                        uint32_t b0, uint32_t b1) {
    asm volatile("mma.sync.aligned.m16n8k16.row.col.f32.f16.f16.f32 "
        "{%0,%1,%2,%3}, {%4,%5,%6,%7}, {%8,%9}, {%0,%1,%2,%3};"
        : "+f"(d[0]), "+f"(d[1]), "+f"(d[2]), "+f"(d[3])
        : "r"(a0), "r"(a1), "r"(a2), "r"(a3), "r"(b0), "r"(b1));
}
__device__ __forceinline__ void ldsm4(uint32_t& r0, uint32_t& r1,
                                      uint32_t& r2, uint32_t& r3,
                                      const void* p) {
    uint32_t a = (uint32_t)__cvta_generic_to_shared(p);
    asm volatile("ldmatrix.sync.aligned.m8n8.x4.shared.b16 {%0,%1,%2,%3}, [%4];"
        : "=r"(r0), "=r"(r1), "=r"(r2), "=r"(r3) : "r"(a));
}
__device__ __forceinline__ void ldsm4_t(uint32_t& r0, uint32_t& r1,
                                        uint32_t& r2, uint32_t& r3,
                                        const void* p) {
    uint32_t a = (uint32_t)__cvta_generic_to_shared(p);
    asm volatile("ldmatrix.sync.aligned.m8n8.x4.trans.shared.b16 {%0,%1,%2,%3}, [%4];"
        : "=r"(r0), "=r"(r1), "=r"(r2), "=r"(r3) : "r"(a));
}
__device__ __forceinline__ void cpa16(void* sdst, const void* gsrc) {
    uint32_t s = (uint32_t)__cvta_generic_to_shared(sdst);
    asm volatile("cp.async.cg.shared.global [%0], [%1], 16;"
                 :: "r"(s), "l"(gsrc) : "memory");
}
#define CP_COMMIT() asm volatile("cp.async.commit_group;" ::: "memory")
#define CP_WAIT0()  asm volatile("cp.async.wait_group 0;" ::: "memory")

// ---------------- weight f16 conversion --------------------------------------
__global__ void __launch_bounds__(256) prep_w(
    const float* __restrict__ wqkv, const float* __restrict__ wo,
    const float* __restrict__ w1,   const float* __restrict__ w2)
{
    for (int i = blockIdx.x*256 + threadIdx.x; i < 131072; i += gridDim.x*256) {
        float v;
        if (i < 49152)       v = wqkv[i];
        else if (i < 65536)  v = wo[i - 49152];
        else if (i < 98304)  v = w1[i - 65536];
        else                 v = w2[i - 98304];
        g_wh[i] = __float2half_rn(v);
    }
}

// ---------------- pair-mask bitmatrix ----------------------------------------
__global__ void __launch_bounds__(256) mask_kernel(const int* __restrict__ nodeT)
{
    __shared__ int smac[2048];
    __shared__ int sjob[2048];
    int tid = threadIdx.x;
    for (int i = tid; i < 2048; i += 256) {
        smac[i] = nodeT[i*3 + 2];
        sjob[i] = nodeT[i*3 + 0];
    }
    __syncthreads();
    int w = tid >> 5, lane = tid & 31;
    int qr = blockIdx.x * 8 + w;
    int mq = smac[qr], jq = sjob[qr];
    for (int wd = 0; wd < 64; wd++) {
        int kk = wd*32 + lane;
        int bit = (mq != smac[kk]) & (jq != sjob[kk]);
        uint32_t word = __ballot_sync(0xffffffffu, bit);
        if (lane == 0) g_mask[qr*64 + wd] = word;
    }
}

// ---------------- fused dual LayerNorm (f16 out) -----------------------------
__global__ void __launch_bounds__(256) ln_kernel(
    const float* __restrict__ x, const float* __restrict__ emb,
    const float* __restrict__ g, const float* __restrict__ bta)
{
    int row  = blockIdx.x * 8 + (threadIdx.x >> 5);
    int lane = threadIdx.x & 31;
    size_t base = (size_t)row * 32 + lane;

    float4 xv = ((const float4*)x)[base];
    float4 ev = ((const float4*)emb)[base];
    float4 g4 = ((const float4*)g)[lane];
    float4 b4 = ((const float4*)bta)[lane];

    float4 t = make_float4(xv.x+ev.x, xv.y+ev.y, xv.z+ev.z, xv.w+ev.w);
    float s = t.x + t.y + t.z + t.w;
    #pragma unroll
    for (int o = 16; o; o >>= 1) s += __shfl_xor_sync(0xffffffffu, s, o);
    float mu = s * (1.0f/128.0f);
    float dx = t.x-mu, dy = t.y-mu, dz = t.z-mu, dw = t.w-mu;
    float v2 = dx*dx + dy*dy + dz*dz + dw*dw;
    #pragma unroll
    for (int o = 16; o; o >>= 1) v2 += __shfl_xor_sync(0xffffffffu, v2, o);
    float r = rsqrtf(v2 * (1.0f/128.0f) + 1e-5f);
    ((uint2*)g_qk_h)[base] = make_uint2(
        pack_f16(dy*r*g4.y + b4.y, dx*r*g4.x + b4.x),
        pack_f16(dw*r*g4.w + b4.w, dz*r*g4.z + b4.z));

    s = xv.x + xv.y + xv.z + xv.w;
    #pragma unroll
    for (int o = 16; o; o >>= 1) s += __shfl_xor_sync(0xffffffffu, s, o);
    mu = s * (1.0f/128.0f);
    dx = xv.x-mu; dy = xv.y-mu; dz = xv.z-mu; dw = xv.w-mu;
    v2 = dx*dx + dy*dy + dz*dz + dw*dw;
    #pragma unroll
    for (int o = 16; o; o >>= 1) v2 += __shfl_xor_sync(0xffffffffu, v2, o);
    r = rsqrtf(v2 * (1.0f/128.0f) + 1e-5f);
    ((uint2*)g_v_h)[base] = make_uint2(
        pack_f16(dy*r*g4.y + b4.y, dx*r*g4.x + b4.x),
        pack_f16(dw*r*g4.w + b4.w, dz*r*g4.z + b4.z));
}

// ================= f16 tensor-core GEMM: C = A(MxK) * W(NxK)^T + bias =======
// CTA tile 128x128, k-chunk 64 (double-buffered cp.async), 8 warps = 4x2,
// warp tile 32x64. Swizzled tiles + ldmatrix.
// MODE 2: out[r,n] = addsrc[r,n] + val (f32); if outh, also f16 copy
// MODE 3: outh[r,n] = f16(2*relu(val))
// MODE 4: fused QKV: grid.y<2 -> A (q/k), grid.y==2 -> A2 (v); all (b,h,s,dh)
template<int MODE>
__global__ void __launch_bounds__(256, 2) gemm_f16k(
    const __half* __restrict__ A, const __half* __restrict__ A2,
    const __half* __restrict__ W, const float* __restrict__ bias,
    const float* __restrict__ addsrc, float* __restrict__ out,
    __half* __restrict__ outh, int N, int K,
    __half* __restrict__ p0, __half* __restrict__ p1, __half* __restrict__ p2)
{
    extern __shared__ uint4 dsm[];
    uint4* As = dsm;          // [2][1024]: 128 rows x 8 chunks(16B), swizzled
    uint4* Ws = dsm + 2048;   // [2][1024]

    int m0 = blockIdx.x * 128, n0 = blockIdx.y * 128;
    int tid = threadIdx.x;
    int w = tid >> 5, lane = tid & 31, g = lane >> 2, tg = lane & 3;
    int wm = w >> 1, wn = w & 1;

    const __half* Asrc = (MODE == 4 && blockIdx.y == 2) ? A2 : A;

    float c[2][8][4];
    #pragma unroll
    for (int mt = 0; mt < 2; mt++)
        #pragma unroll
        for (int j = 0; j < 8; j++)
            #pragma unroll
            for (int i = 0; i < 4; i++) c[mt][j][i] = 0.f;

    #pragma unroll
    for (int it = 0; it < 4; it++) {
        int i = tid + 256*it;
        int r = i >> 3, cc = i & 7;
        int sd = r*8 + (cc ^ (r & 7));
        cpa16(&As[sd], Asrc + (size_t)(m0 + r)*K + cc*8);
        cpa16(&Ws[sd], W    + (size_t)(n0 + r)*K + cc*8);
    }
    CP_COMMIT();

    int nch = K >> 6;
    int la15 = lane & 15, xq = lane & 7, cbq = lane >> 4;
    int rowk = (lane & 7) + 8*(lane >> 4);
    int cbk  = (lane >> 3) & 1;
    int xk   = rowk & 7;

    for (int ic = 0; ic < nch; ic++) {
        CP_WAIT0();
        __syncthreads();
        int cur = ic & 1;
        if (ic + 1 < nch) {
            int nb = cur ^ 1, kc = (ic + 1) * 64;
            #pragma unroll
            for (int it = 0; it < 4; it++) {
                int i = tid + 256*it;
                int r = i >> 3, cc = i & 7;
                int sd = nb*1024 + r*8 + (cc ^ (r & 7));
                cpa16(&As[sd], Asrc + (size_t)(m0 + r)*K + kc + cc*8);
                cpa16(&Ws[sd], W    + (size_t)(n0 + r)*K + kc + cc*8);
            }
            CP_COMMIT();
        }
        const uint4* Ac = As + cur*1024;
        const uint4* Wc = Ws + cur*1024;

        #pragma unroll
        for (int ks = 0; ks < 4; ks++) {
            uint32_t a[2][4];
            #pragma unroll
            for (int mt = 0; mt < 2; mt++)
                ldsm4(a[mt][0], a[mt][1], a[mt][2], a[mt][3],
                      Ac + (32*wm + 16*mt + la15)*8 + ((2*ks + cbq) ^ xq));
            int ck = (2*ks + cbk) ^ xk;
            #pragma unroll
            for (int J = 0; J < 4; J++) {
                uint32_t b0, b1, b2, b3;
                ldsm4(b0, b1, b2, b3, Wc + (64*wn + J*16 + rowk)*8 + ck);
                #pragma unroll
                for (int mt = 0; mt < 2; mt++) {
                    mma_f16(c[mt][2*J],   a[mt][0], a[mt][1], a[mt][2], a[mt][3], b0, b1);
                    mma_f16(c[mt][2*J+1], a[mt][0], a[mt][1], a[mt][2], a[mt][3], b2, b3);
                }
            }
        }
    }

    // ---- epilogue ----
    #pragma unroll
    for (int mt = 0; mt < 2; mt++) {
        int r0 = m0 + 32*wm + 16*mt + g;
        int r1 = r0 + 8;
        #pragma unroll
        for (int j = 0; j < 8; j++) {
            int n = n0 + 64*wn + 8*j + 2*tg;
            float2 bs = *(const float2*)(bias + n);
            float v00 = c[mt][j][0] + bs.x, v01 = c[mt][j][1] + bs.y;
            float v10 = c[mt][j][2] + bs.x, v11 = c[mt][j][3] + bs.y;
            if (MODE == 4) {
                int b0i = r0 >> 11, s0i = r0 & 2047;
                int b1i = r1 >> 11, s1i = r1 & 2047;
                float sc = (n < 128) ? QSCALE : 1.f;
                __half* dst = (n < 128) ? p0 : ((n < 256) ? p1 : p2);
                int e = n & 127, hh = e >> 6, dh = e & 63;
                *(uint32_t*)&dst[((size_t)(b0i*2 + hh)*2048 + s0i)*64 + dh] =
                    pack_f16(v01*sc, v00*sc);
                *(uint32_t*)&dst[((size_t)(b1i*2 + hh)*2048 + s1i)*64 + dh] =
                    pack_f16(v11*sc, v10*sc);
            } else if (MODE == 2) {
                float2 s0 = *(const float2*)(addsrc + (size_t)r0*N + n);
                float2 s1 = *(const float2*)(addsrc + (size_t)r1*N + n);
                float f00 = s0.x + v00, f01 = s0.y + v01;
                float f10 = s1.x + v10, f11 = s1.y + v11;
                *(float2*)(out + (size_t)r0*N + n) = make_float2(f00, f01);
                *(float2*)(out + (size_t)r1*N + n) = make_float2(f10, f11);
                if (outh) {
                    *(uint32_t*)&outh[(size_t)r0*N + n] = pack_f16(f01, f00);
                    *(uint32_t*)&outh[(size_t)r1*N + n] = pack_f16(f11, f10);
                }
            } else {   // MODE 3
                float f00 = 2.f*fmaxf(v00, 0.f), f01 = 2.f*fmaxf(v01, 0.f);
                float f10 = 2.f*fmaxf(v10, 0.f), f11 = 2.f*fmaxf(v11, 0.f);
                *(uint32_t*)&outh[(size_t)r0*N + n] = pack_f16(f01, f00);
                *(uint32_t*)&outh[(size_t)r1*N + n] = pack_f16(f11, f10);
            }
        }
    }
}

// ================= f16 ldmatrix flash attention ==============================
// grid (S/128, B*H), 256 threads (8 warps). Q tile 128, K tile 64, DH=64.
// Q fragments hoisted to registers; V loaded (s,dh) with ldmatrix.trans.
#define ONES16 0x3C003C00u

__global__ void __launch_bounds__(256, 2) attn_f16_kernel(
    const __half* __restrict__ q, const __half* __restrict__ k,
    const __half* __restrict__ v, const int* __restrict__ actions,
    __half* __restrict__ ctxh)
{
    __shared__ uint4 Qs[1024];     // 128 rows x 128B (q rows x dh), swizzled
    __shared__ uint4 Ks[2][512];   // 64 rows (kcol) x 128B (dh)
    __shared__ uint4 Vs[2][512];   // 64 rows (kcol) x 128B (dh)

    int tid = threadIdx.x;
    int w = tid >> 5, lane = tid & 31;
    int g = lane >> 2, tg = lane & 3;
    int bh = blockIdx.y, b = bh >> 1, h = bh & 1;
    int q0 = blockIdx.x * 128;

    const uint4* qg = (const uint4*)(q + ((size_t)bh * S_ + q0) * 64);
    #pragma unroll
    for (int it = 0; it < 4; it++) {
        int i = tid + 256*it;
        int r = i >> 3, cc = i & 7;
        Qs[r*8 + (cc ^ (r & 7))] = qg[i];
    }

    int rq0 = q0 + 16*w + g, rq1 = rq0 + 8;
    int aq0 = (actions[b*S_ + rq0] == 0);
    int aq1 = (actions[b*S_ + rq1] == 0);
    const uint32_t* mr0 = g_mask + rq0*64;
    const uint32_t* mr1 = g_mask + rq1*64;
    uint32_t nw00 = mr0[0], nw01 = mr0[1];
    uint32_t nw10 = mr1[0], nw11 = mr1[1];

    const uint4* kg = (const uint4*)(k + (size_t)bh * S_ * 64);
    const uint4* vg = (const uint4*)(v + (size_t)bh * S_ * 64);

    int fr = tid >> 2, fq = tid & 3;
    int sx0 = fr*8 + ((2*fq)   ^ (fr & 7));
    int sx1 = fr*8 + ((2*fq+1) ^ (fr & 7));

    cpa16(&Ks[0][sx0], kg + (size_t)fr*8 + 2*fq);
    cpa16(&Ks[0][sx1], kg + (size_t)fr*8 + 2*fq + 1);
    cpa16(&Vs[0][sx0], vg + (size_t)fr*8 + 2*fq);
    cpa16(&Vs[0][sx1], vg + (size_t)fr*8 + 2*fq + 1);
    CP_COMMIT();
    __syncthreads();    // Q tile visible

    // ---- hoist Q fragments (constant across K loop) ----
    int rowq = 16*w + (lane & 7) + 8*((lane >> 3) & 1);
    int cbq  = lane >> 4;
    int xq   = rowq & 7;
    uint32_t qf[4][4];
    #pragma unroll
    for (int ks = 0; ks < 4; ks++)
        ldsm4(qf[ks][0], qf[ks][1], qf[ks][2], qf[ks][3],
              Qs + rowq*8 + ((2*ks + cbq) ^ xq));

    // K fragment geometry (B, non-trans)
    int rowk = (lane & 7) + 8*(lane >> 4);
    int cbk  = (lane >> 3) & 1;
    int xk   = rowk & 7;
    // V fragment geometry (B, trans): rows = kcol, chunks = dh
    int rv   = (lane & 7) + 8*((lane >> 3) & 1);
    int cv   = lane >> 4;
    int xv   = lane & 7;

    float o[8][4];
    #pragma unroll
    for (int j = 0; j < 8; j++)
        #pragma unroll
        for (int i = 0; i < 4; i++) o[j][i] = 0.f;
    float o9[4] = {0.f, 0.f, 0.f, 0.f};

    for (int kt = 0; kt < 32; kt++) {
        CP_WAIT0();
        __syncthreads();
        int cur = kt & 1;
        if (kt < 31) {
            int kn = (kt + 1) * 64, nb = cur ^ 1;
            cpa16(&Ks[nb][sx0], kg + (size_t)(kn + fr)*8 + 2*fq);
            cpa16(&Ks[nb][sx1], kg + (size_t)(kn + fr)*8 + 2*fq + 1);
            cpa16(&Vs[nb][sx0], vg + (size_t)(kn + fr)*8 + 2*fq);
            cpa16(&Vs[nb][sx1], vg + (size_t)(kn + fr)*8 + 2*fq + 1);
            CP_COMMIT();
        }
        const uint4* akrow = Ks[cur] + rowk*8;
        const uint4* avbase = Vs[cur];

        // ---- S = Q K^T ----
        float c[8][4];
        #pragma unroll
        for (int j = 0; j < 8; j++)
            #pragma unroll
            for (int i = 0; i < 4; i++) c[j][i] = 0.f;
        #pragma unroll
        for (int ks = 0; ks < 4; ks++) {
            int ck = (2*ks + cbk) ^ xk;
            #pragma unroll
            for (int J = 0; J < 4; J++) {
                uint32_t b0, b1, b2, b3;
                ldsm4(b0, b1, b2, b3, akrow + J*128 + ck);
                mma_f16(c[2*J],   qf[ks][0], qf[ks][1], qf[ks][2], qf[ks][3], b0, b1);
                mma_f16(c[2*J+1], qf[ks][0], qf[ks][1], qf[ks][2], qf[ks][3], b2, b3);
            }
        }

        // ---- mask words (actions folded; pre-shifted by 2*tg) ----
        uint32_t wsh00 = aq0 ? (nw00 >> (2*tg)) : 0u;
        uint32_t wsh01 = aq0 ? (nw01 >> (2*tg)) : 0u;
        uint32_t wsh10 = aq1 ? (nw10 >> (2*tg)) : 0u;
        uint32_t wsh11 = aq1 ? (nw11 >> (2*tg)) : 0u;
        if (kt < 31) {
            nw00 = mr0[kt*2 + 2]; nw01 = mr0[kt*2 + 3];
            nw10 = mr1[kt*2 + 2]; nw11 = mr1[kt*2 + 3];
        }

        // ---- masked exp: p packed f16x2 = PV A-fragments ----
        uint32_t pj0[8], pj1[8];
        #pragma unroll
        for (int j = 0; j < 8; j++) {
            uint32_t w0 = (j < 4) ? wsh00 : wsh01;
            uint32_t w1 = (j < 4) ? wsh10 : wsh11;
            int sh = 8*(j & 3);
            uint32_t bt0 = w0 >> sh, bt1 = w1 >> sh;
            float s00 = (bt0 & 1u) ? -100.f : c[j][0];
            float s01 = (bt0 & 2u) ? -100.f : c[j][1];
            float s10 = (bt1 & 1u) ? -100.f : c[j][2];
            float s11 = (bt1 & 2u) ? -100.f : c[j][3];
            pj0[j] = ex2h2(pack_f16(s01, s00));
            pj1[j] = ex2h2(pack_f16(s11, s10));
        }

        // ---- O += P V (V via ldmatrix.trans); l += P * ones ----
        #pragma unroll
        for (int ks = 0; ks < 4; ks++) {
            uint32_t a0 = pj0[2*ks],   a1 = pj1[2*ks];
            uint32_t a2 = pj0[2*ks+1], a3 = pj1[2*ks+1];
            mma_f16(o9, a0, a1, a2, a3, ONES16, ONES16);
            #pragma unroll
            for (int J = 0; J < 4; J++) {
                uint32_t b0, b1, b2, b3;
                ldsm4_t(b0, b1, b2, b3,
                        avbase + (16*ks + rv)*8 + ((2*J + cv) ^ xv));
                mma_f16(o[2*J],   a0, a1, a2, a3, b0, b1);
                mma_f16(o[2*J+1], a0, a1, a2, a3, b2, b3);
            }
        }
    }

    float inv0 = 1.0f / o9[0];
    float inv1 = 1.0f / o9[2];

    __half* og0 = ctxh + ((size_t)b*S_ + rq0)*128 + h*64;
    __half* og1 = ctxh + ((size_t)b*S_ + rq1)*128 + h*64;
    #pragma unroll
    for (int j = 0; j < 8; j++) {
        int c0 = 8*j + 2*tg;
        *(uint32_t*)(og0 + c0) = pack_f16(o[j][1]*inv0, o[j][0]*inv0);
        *(uint32_t*)(og1 + c0) = pack_f16(o[j][3]*inv1, o[j][2]*inv1);
    }
}

// ---------------- launcher ---------------------------------------------------
extern "C" void kernel_launch(void* const* d_in, const int* in_sizes, int n_in,
                              void* d_out, int out_size)
{
    const float* x    = (const float*)d_in[0];
    const float* emb  = (const float*)d_in[1];
    const int*   act  = (const int*)  d_in[2];
    const int*   node = (const int*)  d_in[3];
    const float* Wqkv = (const float*)d_in[4];
    const float* bqkv = (const float*)d_in[5];
    const float* Wo   = (const float*)d_in[6];
    const float* bo   = (const float*)d_in[7];
    const float* lng  = (const float*)d_in[8];
    const float* lnb  = (const float*)d_in[9];
    const float* W1   = (const float*)d_in[10];
    const float* b1   = (const float*)d_in[11];
    const float* W2   = (const float*)d_in[12];
    const float* b2   = (const float*)d_in[13];
    float* out = (float*)d_out;

    __half *qkh, *vh, *qp, *kp, *vp, *ctxh, *x2h, *hbh, *wh;
    float *x2;
    cudaGetSymbolAddress((void**)&qkh,  g_qk_h);
    cudaGetSymbolAddress((void**)&vh,   g_v_h);
    cudaGetSymbolAddress((void**)&qp,   g_q);
    cudaGetSymbolAddress((void**)&kp,   g_k);
    cudaGetSymbolAddress((void**)&vp,   g_v);
    cudaGetSymbolAddress((void**)&ctxh, g_ctx_h);
    cudaGetSymbolAddress((void**)&x2,   g_x2);
    cudaGetSymbolAddress((void**)&x2h,  g_x2_h);
    cudaGetSymbolAddress((void**)&hbh,  g_hb_h);
    cudaGetSymbolAddress((void**)&wh,   g_wh);

    cudaFuncSetAttribute(gemm_f16k<2>, cudaFuncAttributeMaxDynamicSharedMemorySize, 65536);
    cudaFuncSetAttribute(gemm_f16k<3>, cudaFuncAttributeMaxDynamicSharedMemorySize, 65536);
    cudaFuncSetAttribute(gemm_f16k<4>, cudaFuncAttributeMaxDynamicSharedMemorySize, 65536);

    prep_w<<<128, 256>>>(Wqkv, Wo, W1, W2);
    mask_kernel<<<256, 256>>>(node);
    ln_kernel<<<ROWS/8, 256>>>(x, emb, lng, lnb);

    // fused QKV projection (f16): y<2 -> q/k from qk_h, y==2 -> v from v_h
    gemm_f16k<4><<<dim3(ROWS/128, 3), 256, 65536>>>(
        qkh, vh, wh + WOFF_QKV, bqkv, nullptr, nullptr, nullptr,
        384, 128, qp, kp, vp);

    attn_f16_kernel<<<dim3(S_/128, 16), 256>>>(qp, kp, vp, act, ctxh);

    // out projection + residual: x2 = x + ctx @ Wo^T + bo  (f32 + f16 copy)
    gemm_f16k<2><<<dim3(ROWS/128, 1), 256, 65536>>>(
        ctxh, nullptr, wh + WOFF_O, bo, x, x2, x2h,
        128, 128, nullptr, nullptr, nullptr);
    // FFN1: hb = 2*relu(x2 @ W1^T + b1)  (f16)
    gemm_f16k<3><<<dim3(ROWS/128, 2), 256, 65536>>>(
        x2h, nullptr, wh + WOFF_1, b1, nullptr, nullptr, hbh,
        256, 128, nullptr, nullptr, nullptr);
    // FFN2 + residual: out = x2 + hb @ W2^T + b2  (f32)
    gemm_f16k<2><<<dim3(ROWS/128, 1), 256, 65536>>>(
        hbh, nullptr, wh + WOFF_2, b2, x2, out, nullptr,
        128, 256, nullptr, nullptr, nullptr);
}